// round 11
// baseline (speedup 1.0000x reference)
#include <cuda_runtime.h>
#include <cuda_bf16.h>
#include <cuda_fp8.h>
#include <math_constants.h>
#include <stdint.h>

// Problem constants
#define D      768
#define NA     4096
#define NC     50000
#define NCEN   10000
#define TK     16
#define TKP    64          // per-split top-k kept (fp8 noise slack)
#define RID    96          // global refine-list size

// splits
#define NSPLIT   8
#define CHUNK    (NC / NSPLIT)        // 6250
#define NSPLIT_C 8
#define CHUNK_C  (NCEN / NSPLIT_C)    // 1250

// MMA tiling (fp8 e4m3, m16n8k32)
#define BM 64
#define BN 128
#define BKB 64             // K bytes per chunk (64 e4m3)
#define NKC (D / BKB)      // 12 chunks
#define SPAD 80            // bytes per smem row (16B-aligned, conflict-free 4B LDS)
#define ASTG (BM * SPAD)   // 5120
#define BSTG (BN * SPAD)   // 10240
#define STGB (ASTG + BSTG) // 15360 per stage

#define CAP 128            // per-tile append buffer = BN (cannot overflow)

// ---- scratch (static __device__ globals) ----
__device__ __align__(16) uint8_t g_Af8[NA * D];
__device__ __align__(16) uint8_t g_Candf8[(size_t)NC * D];
__device__ __align__(16) uint8_t g_Cenf8[NCEN * D];

__device__ float g_pv[NA * NSPLIT * TKP];
__device__ int   g_pi[NA * NSPLIT * TKP];
__device__ int   g_ridx[NA * RID];
__device__ float g_cmv[NA * NSPLIT_C * 2];
__device__ int   g_cmi[NA * NSPLIT_C * 2];
__device__ float g_c2[NCEN];
__device__ int   g_fidx[NA * TK];

__device__ __forceinline__ bool precede(float v1, int i1, float v2, int i2) {
    return (v1 > v2) || (v1 == v2 && i1 < i2);
}
__device__ __forceinline__ bool preceded(double v1, int i1, double v2, int i2) {
    return (v1 > v2) || (v1 == v2 && i1 < i2);
}

__device__ __forceinline__ void mma_f8(float* c, const uint32_t* a, const uint32_t* b) {
    asm volatile(
        "mma.sync.aligned.m16n8k32.row.col.f32.e4m3.e4m3.f32 "
        "{%0,%1,%2,%3}, {%4,%5,%6,%7}, {%8,%9}, {%0,%1,%2,%3};"
        : "+f"(c[0]), "+f"(c[1]), "+f"(c[2]), "+f"(c[3])
        : "r"(a[0]), "r"(a[1]), "r"(a[2]), "r"(a[3]), "r"(b[0]), "r"(b[1]));
}
__device__ __forceinline__ void cpz16(uint32_t dst, const void* src, bool ok) {
    asm volatile("cp.async.cg.shared.global [%0], [%1], 16, %2;"
                 :: "r"(dst), "l"(src), "r"(ok ? 16 : 0) : "memory");
}
#define CP_COMMIT()  asm volatile("cp.async.commit_group;" ::: "memory")
#define CP_WAIT(n)   asm volatile("cp.async.wait_group %0;" :: "n"(n) : "memory")

// ---------------------------------------------------------------------------
// float -> e4m3 conversion (4 elems per thread)
// ---------------------------------------------------------------------------
__global__ void k_cvt8(const float4* __restrict__ s, uchar4* __restrict__ d, int n4) {
    int i = blockIdx.x * blockDim.x + threadIdx.x;
    if (i >= n4) return;
    float4 v = s[i];
    uchar4 o;
    o.x = (uint8_t)__nv_cvt_float_to_fp8(v.x, __NV_SATFINITE, __NV_E4M3);
    o.y = (uint8_t)__nv_cvt_float_to_fp8(v.y, __NV_SATFINITE, __NV_E4M3);
    o.z = (uint8_t)__nv_cvt_float_to_fp8(v.z, __NV_SATFINITE, __NV_E4M3);
    o.w = (uint8_t)__nv_cvt_float_to_fp8(v.w, __NV_SATFINITE, __NV_E4M3);
    d[i] = o;
}

// ---------------------------------------------------------------------------
// ||center||^2 precompute (fp32, pruning only)
// ---------------------------------------------------------------------------
__global__ void k_c2(const float* __restrict__ cen) {
    int w = (blockIdx.x * blockDim.x + threadIdx.x) >> 5;
    int lane = threadIdx.x & 31;
    if (w >= NCEN) return;
    const float* p = cen + (size_t)w * D;
    float s = 0.f;
    for (int k = lane; k < D; k += 32) { float x = p[k]; s += x * x; }
    #pragma unroll
    for (int o = 16; o; o >>= 1) s += __shfl_down_sync(0xffffffffu, s, o);
    if (lane == 0) g_c2[w] = s;
}

// ---------------------------------------------------------------------------
// chunk loader: A[64 rows][64B] + B[128 rows][64B] into stage st
// ---------------------------------------------------------------------------
__device__ __forceinline__ void load_chunk(uint32_t sbase, int st, int kt,
                                           int rowBase, int colBase, int colLimit,
                                           const uint8_t* __restrict__ Bsrc) {
    int tid = threadIdx.x;
    uint32_t sA = sbase + st * STGB;
    uint32_t sB = sA + ASTG;
    // A: 64 rows x 4 chunks = 256 loads (1/thread)
    {
        int r = tid >> 2, q = tid & 3;
        cpz16(sA + (uint32_t)(r * SPAD + q * 16),
              g_Af8 + (size_t)(rowBase + r) * D + kt + q * 16, true);
    }
    // B: 128 rows x 4 chunks = 512 loads (2/thread)
    #pragma unroll
    for (int it = 0; it < 2; it++) {
        int u = tid + 256 * it;
        int r = u >> 2, q = u & 3;
        int gc = colBase + r;
        bool ok = gc < colLimit;
        cpz16(sB + (uint32_t)(r * SPAD + q * 16),
              Bsrc + (size_t)(ok ? gc : 0) * D + kt + q * 16, ok);
    }
    CP_COMMIT();
}

// ---------------------------------------------------------------------------
// compute one 64B k-chunk: warp tile 32x32, c[2][4][4], 2 ks-steps of k=32
// ---------------------------------------------------------------------------
__device__ __forceinline__ void compute_chunk(const uint8_t* __restrict__ Ab,
                                              const uint8_t* __restrict__ Bb,
                                              float c[2][4][4], int wm, int wn,
                                              int gid, int tig) {
    #pragma unroll
    for (int ks = 0; ks < 2; ks++) {
        int k0 = ks * 32;
        uint32_t af[2][4], fb[4][2];
        #pragma unroll
        for (int i = 0; i < 2; i++) {
            int r = wm * 32 + i * 16 + gid;
            af[i][0] = *(const uint32_t*)(Ab + r * SPAD + k0 + 4 * tig);
            af[i][1] = *(const uint32_t*)(Ab + (r + 8) * SPAD + k0 + 4 * tig);
            af[i][2] = *(const uint32_t*)(Ab + r * SPAD + k0 + 16 + 4 * tig);
            af[i][3] = *(const uint32_t*)(Ab + (r + 8) * SPAD + k0 + 16 + 4 * tig);
        }
        #pragma unroll
        for (int j = 0; j < 4; j++) {
            int n = wn * 32 + j * 8 + gid;
            fb[j][0] = *(const uint32_t*)(Bb + n * SPAD + k0 + 4 * tig);
            fb[j][1] = *(const uint32_t*)(Bb + n * SPAD + k0 + 16 + 4 * tig);
        }
        #pragma unroll
        for (int i = 0; i < 2; i++)
            #pragma unroll
            for (int j = 0; j < 4; j++)
                mma_f8(c[i][j], af[i], fb[j]);
    }
}

// ---------------------------------------------------------------------------
// candidates GEMM (fp8) + fused per-row top-64  grid (NA/64, NSPLIT), 256 thr
// ---------------------------------------------------------------------------
extern __shared__ __align__(16) char smraw[];

__global__ __launch_bounds__(256)
void k_topk(void) {
    uint32_t sbase = (uint32_t)__cvta_generic_to_shared(smraw);
    float* topv   = (float*)(smraw + 2 * STGB);
    int*   topi   = (int*)(topv + BM * TKP);
    float* bufv   = (float*)(topi + BM * TKP);
    int*   bufi   = (int*)(bufv + BM * CAP);
    float* thresh = (float*)(bufi + BM * CAP);
    int*   cnt    = (int*)(thresh + BM);
    int*   nfill  = cnt + BM;

    int tid = threadIdx.x;
    int lane = tid & 31, wid = tid >> 5;
    int gid = lane >> 2, tig = lane & 3;
    int wm = wid & 1, wn = wid >> 1;

    int rowBase = blockIdx.x * BM;
    int split = blockIdx.y;
    int colStart = split * CHUNK;
    int colEnd = colStart + CHUNK;

    if (tid < BM) { thresh[tid] = -CUDART_INF_F; cnt[tid] = 0; nfill[tid] = 0; }
    __syncthreads();

    int nT = (CHUNK + BN - 1) / BN;      // 49
    #pragma unroll 1
    for (int t = 0; t < nT; t++) {
        int colBase = colStart + t * BN;
        float c[2][4][4];
        #pragma unroll
        for (int i = 0; i < 2; i++)
            #pragma unroll
            for (int j = 0; j < 4; j++)
                #pragma unroll
                for (int f = 0; f < 4; f++) c[i][j][f] = 0.f;

        load_chunk(sbase, 0, 0, rowBase, colBase, colEnd, g_Candf8);
        load_chunk(sbase, 1, BKB, rowBase, colBase, colEnd, g_Candf8);
        #pragma unroll 1
        for (int kk = 0; kk < NKC; kk++) {
            int cur = kk & 1;
            if (kk + 1 < NKC) { CP_WAIT(1); } else { CP_WAIT(0); }
            __syncthreads();
            const uint8_t* Ab = (const uint8_t*)(smraw + cur * STGB);
            const uint8_t* Bb = Ab + ASTG;
            compute_chunk(Ab, Bb, c, wm, wn, gid, tig);
            __syncthreads();
            if (kk + 2 < NKC)
                load_chunk(sbase, cur, (kk + 2) * BKB, rowBase, colBase, colEnd, g_Candf8);
        }

        // epilogue: append above-threshold candidates
        #pragma unroll
        for (int i = 0; i < 2; i++) {
            #pragma unroll
            for (int f = 0; f < 4; f++) {
                int lr = wm * 32 + i * 16 + (f >> 1) * 8 + gid;
                int grow = rowBase + lr;
                float thv = thresh[lr];
                #pragma unroll
                for (int j = 0; j < 4; j++) {
                    int gc = colBase + wn * 32 + j * 8 + 2 * tig + (f & 1);
                    float v = c[i][j][f];
                    if (gc < colEnd && gc != grow && v > thv) {
                        int slot = atomicAdd(&cnt[lr], 1);
                        if (slot < CAP) { bufv[lr * CAP + slot] = v; bufi[lr * CAP + slot] = gc; }
                    }
                }
            }
        }
        __syncthreads();
        // compaction: one thread per row
        if (tid < BM) {
            int cc = cnt[tid];
            if (cc > 0) {
                if (cc > CAP) cc = CAP;
                int nf = nfill[tid];
                float* tv = topv + tid * TKP;
                int*   ti = topi + tid * TKP;
                for (int s = 0; s < cc; s++) {
                    float v = bufv[tid * CAP + s];
                    int gi = bufi[tid * CAP + s];
                    if (nf == TKP && !precede(v, gi, tv[TKP - 1], ti[TKP - 1])) continue;
                    int p = (nf < TKP) ? nf : TKP - 1;
                    while (p > 0 && precede(v, gi, tv[p - 1], ti[p - 1])) {
                        tv[p] = tv[p - 1]; ti[p] = ti[p - 1]; p--;
                    }
                    tv[p] = v; ti[p] = gi;
                    if (nf < TKP) nf++;
                }
                nfill[tid] = nf;
                cnt[tid] = 0;
                if (nf == TKP) thresh[tid] = tv[TKP - 1];
            }
        }
        __syncthreads();
    }
    if (tid < BM) {
        int row = rowBase + tid;
        int nf = nfill[tid];
        for (int k2 = 0; k2 < TKP; k2++) {
            g_pv[(row * NSPLIT + split) * TKP + k2] = (k2 < nf) ? topv[tid * TKP + k2] : -CUDART_INF_F;
            g_pi[(row * NSPLIT + split) * TKP + k2] = (k2 < nf) ? topi[tid * TKP + k2] : 0x7fffffff;
        }
    }
}

// ---------------------------------------------------------------------------
// centers GEMM (fp8) + fused min-2 of (c2 - 2*dot)  grid (NA/64, NSPLIT_C)
// ---------------------------------------------------------------------------
__global__ __launch_bounds__(256)
void k_centers(void) {
    uint32_t sbase = (uint32_t)__cvta_generic_to_shared(smraw);
    float* redv = (float*)(smraw + 2 * STGB);
    int*   redi = (int*)(redv + BM * 32);

    int tid = threadIdx.x;
    int lane = tid & 31, wid = tid >> 5;
    int gid = lane >> 2, tig = lane & 3;
    int wm = wid & 1, wn = wid >> 1;

    int rowBase = blockIdx.x * BM;
    int split = blockIdx.y;
    int colStart = split * CHUNK_C;
    int colEnd = colStart + CHUNK_C;

    float bv0[4], bv1[4]; int bi0[4], bi1[4];
    #pragma unroll
    for (int i = 0; i < 4; i++) {
        bv0[i] = bv1[i] = CUDART_INF_F;
        bi0[i] = bi1[i] = 0x7fffffff;
    }

    int nT = (CHUNK_C + BN - 1) / BN;   // 10
    #pragma unroll 1
    for (int t = 0; t < nT; t++) {
        int colBase = colStart + t * BN;
        float c[2][4][4];
        #pragma unroll
        for (int i = 0; i < 2; i++)
            #pragma unroll
            for (int j = 0; j < 4; j++)
                #pragma unroll
                for (int f = 0; f < 4; f++) c[i][j][f] = 0.f;

        load_chunk(sbase, 0, 0, rowBase, colBase, colEnd, g_Cenf8);
        load_chunk(sbase, 1, BKB, rowBase, colBase, colEnd, g_Cenf8);
        #pragma unroll 1
        for (int kk = 0; kk < NKC; kk++) {
            int cur = kk & 1;
            if (kk + 1 < NKC) { CP_WAIT(1); } else { CP_WAIT(0); }
            __syncthreads();
            const uint8_t* Ab = (const uint8_t*)(smraw + cur * STGB);
            const uint8_t* Bb = Ab + ASTG;
            compute_chunk(Ab, Bb, c, wm, wn, gid, tig);
            __syncthreads();
            if (kk + 2 < NKC)
                load_chunk(sbase, cur, (kk + 2) * BKB, rowBase, colBase, colEnd, g_Cenf8);
        }
        // min-2 update
        #pragma unroll
        for (int i = 0; i < 2; i++)
            #pragma unroll
            for (int f = 0; f < 4; f++) {
                int ri = i * 2 + (f >> 1);
                #pragma unroll
                for (int j = 0; j < 4; j++) {
                    int gc = colBase + wn * 32 + j * 8 + 2 * tig + (f & 1);
                    if (gc < colEnd) {
                        float v = g_c2[gc] - 2.0f * c[i][j][f];
                        if (v < bv0[ri] || (v == bv0[ri] && gc < bi0[ri])) {
                            bv1[ri] = bv0[ri]; bi1[ri] = bi0[ri];
                            bv0[ri] = v; bi0[ri] = gc;
                        } else if (v < bv1[ri] || (v == bv1[ri] && gc < bi1[ri])) {
                            bv1[ri] = v; bi1[ri] = gc;
                        }
                    }
                }
            }
    }

    // per-row reduction: 16 thread-columns (wn,tig) hold each row, 2 values each
    int sid = wn * 4 + tig;   // 0..15
    #pragma unroll
    for (int i = 0; i < 2; i++)
        #pragma unroll
        for (int hi = 0; hi < 2; hi++) {
            int ri = i * 2 + hi;
            int lr = wm * 32 + i * 16 + hi * 8 + gid;
            redv[lr * 32 + sid * 2 + 0] = bv0[ri];
            redi[lr * 32 + sid * 2 + 0] = bi0[ri];
            redv[lr * 32 + sid * 2 + 1] = bv1[ri];
            redi[lr * 32 + sid * 2 + 1] = bi1[ri];
        }
    __syncthreads();
    if (tid < BM) {
        float b0 = CUDART_INF_F, b1 = CUDART_INF_F;
        int i0 = 0x7fffffff, i1 = 0x7fffffff;
        for (int x = 0; x < 32; x++) {
            float v = redv[tid * 32 + x]; int ii = redi[tid * 32 + x];
            if (v < b0 || (v == b0 && ii < i0)) { b1 = b0; i1 = i0; b0 = v; i0 = ii; }
            else if (v < b1 || (v == b1 && ii < i1)) { b1 = v; i1 = ii; }
        }
        int row = rowBase + tid;
        g_cmv[(row * NSPLIT_C + split) * 2 + 0] = b0;
        g_cmi[(row * NSPLIT_C + split) * 2 + 0] = i0;
        g_cmv[(row * NSPLIT_C + split) * 2 + 1] = b1;
        g_cmi[(row * NSPLIT_C + split) * 2 + 1] = i1;
    }
}

// ---------------------------------------------------------------------------
// Merge topk partials: bitonic sort of 512 pairs/row, keep top-96
// ---------------------------------------------------------------------------
__global__ void k_mtopk() {
    __shared__ float sv[512];
    __shared__ int   si[512];
    int row = blockIdx.x;
    int tid = threadIdx.x;
    sv[tid] = g_pv[row * 512 + tid];
    si[tid] = g_pi[row * 512 + tid];
    __syncthreads();
    for (int k = 2; k <= 512; k <<= 1) {
        for (int j = k >> 1; j > 0; j >>= 1) {
            int ixj = tid ^ j;
            if (ixj > tid) {
                float v1 = sv[tid], v2 = sv[ixj];
                int i1 = si[tid], i2 = si[ixj];
                bool desc = ((tid & k) == 0);
                bool sw = desc ? precede(v2, i2, v1, i1) : precede(v1, i1, v2, i2);
                if (sw) { sv[tid] = v2; si[tid] = i2; sv[ixj] = v1; si[ixj] = i1; }
            }
            __syncthreads();
        }
    }
    if (tid < RID) g_ridx[row * RID + tid] = si[tid];
}

// ---------------------------------------------------------------------------
// compensated-fp32 dot / dist2 (TwoProd via FMA + Neumaier; exact-class rank)
// ---------------------------------------------------------------------------
__device__ __forceinline__ double comp_dot(const float* __restrict__ a,
                                           const float* __restrict__ b, int lane) {
    float s = 0.f, comp = 0.f;
    for (int k = lane; k < D; k += 32) {
        float x = a[k], y = b[k];
        float p = x * y;
        float e = fmaf(x, y, -p);
        float t = s + p;
        comp += (fabsf(s) >= fabsf(p)) ? ((s - t) + p) : ((p - t) + s);
        s = t;
        comp += e;
    }
    return (double)s + (double)comp;
}

__device__ __forceinline__ double comp_dist2(const float* __restrict__ a,
                                             const float* __restrict__ b, int lane) {
    float s = 0.f, comp = 0.f;
    for (int k = lane; k < D; k += 32) {
        float d = a[k] - b[k];
        float p = d * d;
        float e = fmaf(d, d, -p);
        float t = s + p;
        comp += (fabsf(s) >= fabsf(p)) ? ((s - t) + p) : ((p - t) + s);
        s = t;
        comp += e;
    }
    return (double)s + (double)comp;
}

// ---------------------------------------------------------------------------
// refine top-96 sims -> exact top-16 (one block per anchor row)
// ---------------------------------------------------------------------------
__global__ __launch_bounds__(256)
void k_refine(const float* __restrict__ A, const float* __restrict__ Cand) {
    __shared__ double dv[RID];
    __shared__ int    di[RID];
    int row = blockIdx.x;
    int tid = threadIdx.x;
    int wid = tid >> 5, lane = tid & 31;
    const float* ar = A + (size_t)row * D;
    for (int c = wid; c < RID; c += 8) {
        int idx = g_ridx[row * RID + c];
        double s;
        if (idx >= 0 && idx < NC) {
            s = comp_dot(ar, Cand + (size_t)idx * D, lane);
        } else {
            s = (lane == 0) ? -CUDART_INF : 0.0;
        }
        #pragma unroll
        for (int o = 16; o; o >>= 1) s += __shfl_down_sync(0xffffffffu, s, o);
        if (lane == 0) { dv[c] = s; di[c] = idx; }
    }
    __syncthreads();
    if (tid == 0) {
        double tvv[TK]; int tii[TK]; int nf = 0;
        for (int s = 0; s < RID; s++) {
            double v = dv[s]; int gi = di[s];
            if (nf == TK && !preceded(v, gi, tvv[TK - 1], tii[TK - 1])) continue;
            int p = (nf < TK) ? nf : TK - 1;
            while (p > 0 && preceded(v, gi, tvv[p - 1], tii[p - 1])) {
                tvv[p] = tvv[p - 1]; tii[p] = tii[p - 1]; p--;
            }
            tvv[p] = v; tii[p] = gi;
            if (nf < TK) nf++;
        }
        for (int k2 = 0; k2 < TK; k2++) g_fidx[row * TK + k2] = tii[k2];
    }
}

// ---------------------------------------------------------------------------
// refine 16 center candidates -> exact argmin + min_dist
// ---------------------------------------------------------------------------
__global__ __launch_bounds__(256)
void k_cenref(const float* __restrict__ A, const float* __restrict__ Cen,
              float* __restrict__ out) {
    __shared__ double dv[NSPLIT_C * 2];
    __shared__ int    di[NSPLIT_C * 2];
    int row = blockIdx.x;
    int tid = threadIdx.x;
    int wid = tid >> 5, lane = tid & 31;
    const float* ar = A + (size_t)row * D;
    for (int c = wid; c < NSPLIT_C * 2; c += 8) {
        int idx = g_cmi[row * NSPLIT_C * 2 + c];
        double s;
        if (idx >= 0 && idx < NCEN) {
            s = comp_dist2(ar, Cen + (size_t)idx * D, lane);
        } else {
            s = (lane == 0) ? CUDART_INF : 0.0;
        }
        #pragma unroll
        for (int o = 16; o; o >>= 1) s += __shfl_down_sync(0xffffffffu, s, o);
        if (lane == 0) { dv[c] = s; di[c] = idx; }
    }
    __syncthreads();
    if (tid == 0) {
        double best = CUDART_INF; int besti = 0x7fffffff;
        for (int s = 0; s < NSPLIT_C * 2; s++) {
            double v = dv[s]; int ii = di[s];
            if (v < best || (v == best && ii < besti)) { best = v; besti = ii; }
        }
        if (best < 0.0) best = 0.0;
        out[(size_t)NA * TK * D + row] = (float)besti;
        out[(size_t)NA * TK * D + NA + row] = (float)sqrt(best);
    }
}

// ---------------------------------------------------------------------------
// Gather: out[row][k][:] = candidates[idx][:]
// ---------------------------------------------------------------------------
__global__ void k_gather(const float* __restrict__ Cand, float* __restrict__ out) {
    int b = blockIdx.x;
    int t = threadIdx.x;
    int idx = g_fidx[b];
    const float4* c4 = (const float4*)(Cand + (size_t)idx * D);
    float4* o4 = (float4*)(out + (size_t)b * D);
    o4[t] = c4[t];
}

// ---------------------------------------------------------------------------
extern "C" void kernel_launch(void* const* d_in, const int* in_sizes, int n_in,
                              void* d_out, int out_size) {
    const float* A    = (const float*)d_in[0];   // anchors    [4096, 768]
    const float* Cand = (const float*)d_in[1];   // candidates [50000, 768]
    const float* Cen  = (const float*)d_in[2];   // centers    [10000, 768]
    float* out = (float*)d_out;

    int smem_topk = 2 * STGB + (2 * BM * TKP + 2 * BM * CAP + 3 * BM) * 4;  // 129,792
    int smem_cen  = 2 * STGB + (2 * BM * 32) * 4;                            // 47,104
    cudaFuncSetAttribute(k_topk, cudaFuncAttributeMaxDynamicSharedMemorySize, smem_topk);
    cudaFuncSetAttribute(k_centers, cudaFuncAttributeMaxDynamicSharedMemorySize, smem_cen);

    uint8_t *pA8, *pCand8, *pCen8;
    cudaGetSymbolAddress((void**)&pA8, g_Af8);
    cudaGetSymbolAddress((void**)&pCand8, g_Candf8);
    cudaGetSymbolAddress((void**)&pCen8, g_Cenf8);

    // 0) conversions to fp8 (launches 1-3)
    k_cvt8<<<(NA * D / 4 + 255) / 256, 256>>>((const float4*)A, (uchar4*)pA8, NA * D / 4);
    k_cvt8<<<(NC * D / 4 + 255) / 256, 256>>>((const float4*)Cand, (uchar4*)pCand8, NC * D / 4);
    k_cvt8<<<(NCEN * D / 4 + 255) / 256, 256>>>((const float4*)Cen, (uchar4*)pCen8, NCEN * D / 4);
    // 1) candidates GEMM + top-64 pruning (launch 4 — ncu capture slot)
    k_topk<<<dim3(NA / BM, NSPLIT), 256, smem_topk>>>();
    // 2) ||center||^2
    k_c2<<<(NCEN * 32 + 255) / 256, 256>>>(Cen);
    // 3) centers GEMM + min-2 pruning
    k_centers<<<dim3(NA / BM, NSPLIT_C), 256, smem_cen>>>();
    // 4) merge partials -> refine list (top-96)
    k_mtopk<<<NA, 512>>>();
    // 5) exact top-16 (compensated fp32)
    k_refine<<<NA, 256>>>(A, Cand);
    // 6) exact argmin + min_dist
    k_cenref<<<NA, 256>>>(A, Cen, out);
    // 7) gather hard negatives
    k_gather<<<NA * TK, 192>>>(Cand, out);
}

// round 13
// speedup vs baseline: 2.8301x; 2.8301x over previous
#include <cuda_runtime.h>
#include <cuda_bf16.h>
#include <math_constants.h>
#include <stdint.h>

// Problem constants
#define D      768
#define NA     4096
#define NC     50000
#define NCEN   10000
#define TK     16
#define TKP    32          // kept per split (slack for refine)

// splits
#define NSPLIT   8
#define CHUNK    (NC / NSPLIT)        // 6250
#define NSPLIT_C 8
#define CHUNK_C  (NCEN / NSPLIT_C)    // 1250

// MMA tiling (bf16, m16n8k16) — exact R5 configuration
#define BM 64
#define BN 128
#define BK 32
#define NKC (D / BK)       // 24 k-chunks
#define SAPAD 40           // bf16 elems per smem row (80B stride)
#define SBPAD 40

#define CAP 128            // per-tile append buffer = BN (cannot overflow)

// ---- scratch (static __device__ globals) ----
__device__ __align__(16) uint16_t g_Abf[NA * D];
__device__ __align__(16) uint16_t g_Candbf[(size_t)NC * D];
__device__ __align__(16) uint16_t g_Cenbf[NCEN * D];

__device__ float g_pv[NA * NSPLIT * TKP];
__device__ int   g_pi[NA * NSPLIT * TKP];
__device__ int   g_ridx[NA * TKP];
__device__ float g_cmv[NA * NSPLIT_C * 2];
__device__ int   g_cmi[NA * NSPLIT_C * 2];
__device__ float g_c2[NCEN];
__device__ int   g_fidx[NA * TK];

__device__ __forceinline__ bool precede(float v1, int i1, float v2, int i2) {
    return (v1 > v2) || (v1 == v2 && i1 < i2);
}
__device__ __forceinline__ bool preceded(double v1, int i1, double v2, int i2) {
    return (v1 > v2) || (v1 == v2 && i1 < i2);
}

__device__ __forceinline__ void mma16816(float* c, const uint32_t* a, const uint32_t* b) {
    asm volatile(
        "mma.sync.aligned.m16n8k16.row.col.f32.bf16.bf16.f32 "
        "{%0,%1,%2,%3}, {%4,%5,%6,%7}, {%8,%9}, {%0,%1,%2,%3};"
        : "+f"(c[0]), "+f"(c[1]), "+f"(c[2]), "+f"(c[3])
        : "r"(a[0]), "r"(a[1]), "r"(a[2]), "r"(a[3]), "r"(b[0]), "r"(b[1]));
}
__device__ __forceinline__ void cp16(uint32_t dst, const void* src, int sz) {
    asm volatile("cp.async.cg.shared.global [%0], [%1], 16, %2;"
                 :: "r"(dst), "l"(src), "r"(sz) : "memory");
}
__device__ __forceinline__ void cp_commit() {
    asm volatile("cp.async.commit_group;" ::: "memory");
}

// ---------------------------------------------------------------------------
// float -> bf16 conversion (vectorized)
// ---------------------------------------------------------------------------
__global__ void k_cvt(const float4* __restrict__ s, uint2* __restrict__ d, int n4) {
    int i = blockIdx.x * blockDim.x + threadIdx.x;
    if (i >= n4) return;
    float4 v = s[i];
    __nv_bfloat162 p0 = __floats2bfloat162_rn(v.x, v.y);
    __nv_bfloat162 p1 = __floats2bfloat162_rn(v.z, v.w);
    uint2 o;
    o.x = *(uint32_t*)&p0;
    o.y = *(uint32_t*)&p1;
    d[i] = o;
}

// ---------------------------------------------------------------------------
// ||center||^2 precompute (fp32, pruning only)
// ---------------------------------------------------------------------------
__global__ void k_c2(const float* __restrict__ cen) {
    int w = (blockIdx.x * blockDim.x + threadIdx.x) >> 5;
    int lane = threadIdx.x & 31;
    if (w >= NCEN) return;
    const float* p = cen + (size_t)w * D;
    float s = 0.f;
    for (int k = lane; k < D; k += 32) { float x = p[k]; s += x * x; }
    #pragma unroll
    for (int o = 16; o; o >>= 1) s += __shfl_down_sync(0xffffffffu, s, o);
    if (lane == 0) g_c2[w] = s;
}

// ---------------------------------------------------------------------------
// bf16 MMA GEMM + fused per-row top-32 (partial over a column chunk)
// grid (NA/BM, NSPLIT), 256 threads, dynamic smem     [exact R5 structure]
// ---------------------------------------------------------------------------
extern __shared__ __align__(16) char smraw[];

__global__ __launch_bounds__(256)
void k_topk(void) {
    uint16_t* As = (uint16_t*)smraw;                     // [2][64*SAPAD]
    uint16_t* Bs = As + 2 * 64 * SAPAD;                  // [2][128*SBPAD]
    float* topv   = (float*)(Bs + 2 * 128 * SBPAD);      // [BM][TKP]
    int*   topi   = (int*)(topv + BM * TKP);
    float* bufv   = (float*)(topi + BM * TKP);           // [BM][CAP]
    int*   bufi   = (int*)(bufv + BM * CAP);
    float* thresh = (float*)(bufi + BM * CAP);           // [BM]
    int*   cnt    = (int*)(thresh + BM);
    int*   nfill  = cnt + BM;

    int tid = threadIdx.x;
    int lane = tid & 31, wid = tid >> 5;
    int gid = lane >> 2, tig = lane & 3;
    int wm = wid & 1, wn = wid >> 1;     // warp covers rows wm*32.., cols wn*32..
    int ar = tid >> 2, aq = tid & 3;     // loader mapping

    int rowBase = blockIdx.x * BM;
    int split = blockIdx.y;
    int colStart = split * CHUNK;
    int colEnd = colStart + CHUNK;

    if (tid < BM) { thresh[tid] = -CUDART_INF_F; cnt[tid] = 0; nfill[tid] = 0; }
    __syncthreads();

    uint32_t sA = (uint32_t)__cvta_generic_to_shared(As);
    uint32_t sB = (uint32_t)__cvta_generic_to_shared(Bs);

    int nT = (CHUNK + BN - 1) / BN;
    for (int t = 0; t < nT; t++) {
        int colBase = colStart + t * BN;
        float c[2][4][4];
        #pragma unroll
        for (int i = 0; i < 2; i++)
            #pragma unroll
            for (int j = 0; j < 4; j++)
                #pragma unroll
                for (int f = 0; f < 4; f++) c[i][j][f] = 0.f;

        auto issueAB = [&](int st, int kt) {
            uint32_t dstA = sA + (uint32_t)(st * 64 * SAPAD + ar * SAPAD + aq * 8) * 2;
            const uint16_t* srcA = g_Abf + (size_t)(rowBase + ar) * D + kt + aq * 8;
            cp16(dstA, srcA, 16);
            #pragma unroll
            for (int h = 0; h < 2; h++) {
                int r = ar + h * 64;
                int gc = colBase + r;
                bool ok = gc < colEnd;
                uint32_t dstB = sB + (uint32_t)(st * 128 * SBPAD + r * SBPAD + aq * 8) * 2;
                const uint16_t* srcB = g_Candbf + (size_t)(ok ? gc : 0) * D + kt + aq * 8;
                cp16(dstB, srcB, ok ? 16 : 0);
            }
            cp_commit();
        };

        issueAB(0, 0);
        for (int kk = 0; kk < NKC; kk++) {
            int cur = kk & 1;
            if (kk + 1 < NKC) {
                issueAB((kk + 1) & 1, (kk + 1) * BK);
                asm volatile("cp.async.wait_group 1;" ::: "memory");
            } else {
                asm volatile("cp.async.wait_group 0;" ::: "memory");
            }
            __syncthreads();
            const uint16_t* Ab = As + cur * 64 * SAPAD;
            const uint16_t* Bb = Bs + cur * 128 * SBPAD;
            #pragma unroll
            for (int ks = 0; ks < 2; ks++) {
                int k0 = ks * 16;
                uint32_t af[2][4], fb[4][2];
                #pragma unroll
                for (int i = 0; i < 2; i++) {
                    int r = wm * 32 + i * 16 + gid;
                    af[i][0] = *(const uint32_t*)(Ab + r * SAPAD + k0 + 2 * tig);
                    af[i][1] = *(const uint32_t*)(Ab + (r + 8) * SAPAD + k0 + 2 * tig);
                    af[i][2] = *(const uint32_t*)(Ab + r * SAPAD + k0 + 8 + 2 * tig);
                    af[i][3] = *(const uint32_t*)(Ab + (r + 8) * SAPAD + k0 + 8 + 2 * tig);
                }
                #pragma unroll
                for (int j = 0; j < 4; j++) {
                    int n = wn * 32 + j * 8 + gid;
                    fb[j][0] = *(const uint32_t*)(Bb + n * SBPAD + k0 + 2 * tig);
                    fb[j][1] = *(const uint32_t*)(Bb + n * SBPAD + k0 + 8 + 2 * tig);
                }
                #pragma unroll
                for (int i = 0; i < 2; i++)
                    #pragma unroll
                    for (int j = 0; j < 4; j++)
                        mma16816(c[i][j], af[i], fb[j]);
            }
            __syncthreads();
        }

        // ---- epilogue: append above-threshold candidates ----
        float th[4];
        #pragma unroll
        for (int i = 0; i < 2; i++)
            #pragma unroll
            for (int hi = 0; hi < 2; hi++)
                th[i * 2 + hi] = thresh[wm * 32 + i * 16 + hi * 8 + gid];

        #pragma unroll
        for (int i = 0; i < 2; i++) {
            #pragma unroll
            for (int f = 0; f < 4; f++) {
                int hi = f >> 1;
                int lr = wm * 32 + i * 16 + hi * 8 + gid;
                int grow = rowBase + lr;
                float thv = th[i * 2 + hi];
                #pragma unroll
                for (int j = 0; j < 4; j++) {
                    int gc = colBase + wn * 32 + j * 8 + 2 * tig + (f & 1);
                    float v = c[i][j][f];
                    if (gc < colEnd && gc != grow && v > thv) {
                        int slot = atomicAdd(&cnt[lr], 1);
                        if (slot < CAP) { bufv[lr * CAP + slot] = v; bufi[lr * CAP + slot] = gc; }
                    }
                }
            }
        }
        __syncthreads();
        // ---- compaction: one thread per row ----
        if (tid < BM) {
            int cc = cnt[tid];
            if (cc > 0) {
                if (cc > CAP) cc = CAP;
                int nf = nfill[tid];
                float* tv = topv + tid * TKP;
                int*   ti = topi + tid * TKP;
                for (int s = 0; s < cc; s++) {
                    float v = bufv[tid * CAP + s];
                    int gi = bufi[tid * CAP + s];
                    if (nf == TKP && !precede(v, gi, tv[TKP - 1], ti[TKP - 1])) continue;
                    int p = (nf < TKP) ? nf : TKP - 1;
                    while (p > 0 && precede(v, gi, tv[p - 1], ti[p - 1])) {
                        tv[p] = tv[p - 1]; ti[p] = ti[p - 1]; p--;
                    }
                    tv[p] = v; ti[p] = gi;
                    if (nf < TKP) nf++;
                }
                nfill[tid] = nf;
                cnt[tid] = 0;
                if (nf == TKP) thresh[tid] = tv[TKP - 1];
            }
        }
        __syncthreads();
    }
    if (tid < BM) {
        int row = rowBase + tid;
        int nf = nfill[tid];
        for (int k2 = 0; k2 < TKP; k2++) {
            g_pv[(row * NSPLIT + split) * TKP + k2] = (k2 < nf) ? topv[tid * TKP + k2] : -CUDART_INF_F;
            g_pi[(row * NSPLIT + split) * TKP + k2] = (k2 < nf) ? topi[tid * TKP + k2] : 0x7fffffff;
        }
    }
}

// ---------------------------------------------------------------------------
// bf16 MMA centers GEMM + fused min-2 of (c2 - 2*dot) per split
// grid (NA/BM, NSPLIT_C), 256 threads, static smem     [exact R5 structure]
// ---------------------------------------------------------------------------
__global__ __launch_bounds__(256)
void k_centers(void) {
    __shared__ __align__(16) uint16_t As[2 * 64 * SAPAD];
    __shared__ __align__(16) uint16_t Bs[2 * 128 * SBPAD];
    __shared__ float redv[BM * 32];
    __shared__ int   redi[BM * 32];

    int tid = threadIdx.x;
    int lane = tid & 31, wid = tid >> 5;
    int gid = lane >> 2, tig = lane & 3;
    int wm = wid & 1, wn = wid >> 1;
    int ar = tid >> 2, aq = tid & 3;

    int rowBase = blockIdx.x * BM;
    int split = blockIdx.y;
    int colStart = split * CHUNK_C;
    int colEnd = colStart + CHUNK_C;

    uint32_t sA = (uint32_t)__cvta_generic_to_shared(As);
    uint32_t sB = (uint32_t)__cvta_generic_to_shared(Bs);

    float bv0[4], bv1[4]; int bi0[4], bi1[4];
    #pragma unroll
    for (int i = 0; i < 4; i++) {
        bv0[i] = bv1[i] = CUDART_INF_F;
        bi0[i] = bi1[i] = 0x7fffffff;
    }

    int nT = (CHUNK_C + BN - 1) / BN;
    for (int t = 0; t < nT; t++) {
        int colBase = colStart + t * BN;
        float c[2][4][4];
        #pragma unroll
        for (int i = 0; i < 2; i++)
            #pragma unroll
            for (int j = 0; j < 4; j++)
                #pragma unroll
                for (int f = 0; f < 4; f++) c[i][j][f] = 0.f;

        auto issueAB = [&](int st, int kt) {
            uint32_t dstA = sA + (uint32_t)(st * 64 * SAPAD + ar * SAPAD + aq * 8) * 2;
            const uint16_t* srcA = g_Abf + (size_t)(rowBase + ar) * D + kt + aq * 8;
            cp16(dstA, srcA, 16);
            #pragma unroll
            for (int h = 0; h < 2; h++) {
                int r = ar + h * 64;
                int gc = colBase + r;
                bool ok = gc < colEnd;
                uint32_t dstB = sB + (uint32_t)(st * 128 * SBPAD + r * SBPAD + aq * 8) * 2;
                const uint16_t* srcB = g_Cenbf + (size_t)(ok ? gc : 0) * D + kt + aq * 8;
                cp16(dstB, srcB, ok ? 16 : 0);
            }
            cp_commit();
        };

        issueAB(0, 0);
        for (int kk = 0; kk < NKC; kk++) {
            int cur = kk & 1;
            if (kk + 1 < NKC) {
                issueAB((kk + 1) & 1, (kk + 1) * BK);
                asm volatile("cp.async.wait_group 1;" ::: "memory");
            } else {
                asm volatile("cp.async.wait_group 0;" ::: "memory");
            }
            __syncthreads();
            const uint16_t* Ab = As + cur * 64 * SAPAD;
            const uint16_t* Bb = Bs + cur * 128 * SBPAD;
            #pragma unroll
            for (int ks = 0; ks < 2; ks++) {
                int k0 = ks * 16;
                uint32_t af[2][4], fb[4][2];
                #pragma unroll
                for (int i = 0; i < 2; i++) {
                    int r = wm * 32 + i * 16 + gid;
                    af[i][0] = *(const uint32_t*)(Ab + r * SAPAD + k0 + 2 * tig);
                    af[i][1] = *(const uint32_t*)(Ab + (r + 8) * SAPAD + k0 + 2 * tig);
                    af[i][2] = *(const uint32_t*)(Ab + r * SAPAD + k0 + 8 + 2 * tig);
                    af[i][3] = *(const uint32_t*)(Ab + (r + 8) * SAPAD + k0 + 8 + 2 * tig);
                }
                #pragma unroll
                for (int j = 0; j < 4; j++) {
                    int n = wn * 32 + j * 8 + gid;
                    fb[j][0] = *(const uint32_t*)(Bb + n * SBPAD + k0 + 2 * tig);
                    fb[j][1] = *(const uint32_t*)(Bb + n * SBPAD + k0 + 8 + 2 * tig);
                }
                #pragma unroll
                for (int i = 0; i < 2; i++)
                    #pragma unroll
                    for (int j = 0; j < 4; j++)
                        mma16816(c[i][j], af[i], fb[j]);
            }
            __syncthreads();
        }

        // min-2 update
        #pragma unroll
        for (int i = 0; i < 2; i++)
            #pragma unroll
            for (int f = 0; f < 4; f++) {
                int ri = i * 2 + (f >> 1);
                #pragma unroll
                for (int j = 0; j < 4; j++) {
                    int gc = colBase + wn * 32 + j * 8 + 2 * tig + (f & 1);
                    if (gc < colEnd) {
                        float v = g_c2[gc] - 2.0f * c[i][j][f];
                        if (v < bv0[ri] || (v == bv0[ri] && gc < bi0[ri])) {
                            bv1[ri] = bv0[ri]; bi1[ri] = bi0[ri];
                            bv0[ri] = v; bi0[ri] = gc;
                        } else if (v < bv1[ri] || (v == bv1[ri] && gc < bi1[ri])) {
                            bv1[ri] = v; bi1[ri] = gc;
                        }
                    }
                }
            }
    }

    // reduction across the 16 thread-columns holding each row
    int sid = wn * 4 + tig;   // 0..15
    #pragma unroll
    for (int i = 0; i < 2; i++)
        #pragma unroll
        for (int hi = 0; hi < 2; hi++) {
            int ri = i * 2 + hi;
            int lr = wm * 32 + i * 16 + hi * 8 + gid;
            redv[lr * 32 + sid * 2 + 0] = bv0[ri];
            redi[lr * 32 + sid * 2 + 0] = bi0[ri];
            redv[lr * 32 + sid * 2 + 1] = bv1[ri];
            redi[lr * 32 + sid * 2 + 1] = bi1[ri];
        }
    __syncthreads();
    if (tid < BM) {
        float b0 = CUDART_INF_F, b1 = CUDART_INF_F;
        int i0 = 0x7fffffff, i1 = 0x7fffffff;
        for (int x = 0; x < 32; x++) {
            float v = redv[tid * 32 + x]; int ii = redi[tid * 32 + x];
            if (v < b0 || (v == b0 && ii < i0)) { b1 = b0; i1 = i0; b0 = v; i0 = ii; }
            else if (v < b1 || (v == b1 && ii < i1)) { b1 = v; i1 = ii; }
        }
        int row = rowBase + tid;
        g_cmv[(row * NSPLIT_C + split) * 2 + 0] = b0;
        g_cmi[(row * NSPLIT_C + split) * 2 + 0] = i0;
        g_cmv[(row * NSPLIT_C + split) * 2 + 1] = b1;
        g_cmi[(row * NSPLIT_C + split) * 2 + 1] = i1;
    }
}

// ---------------------------------------------------------------------------
// Merge topk partials: bitonic sort of 256 pairs/row, keep top-32
// ---------------------------------------------------------------------------
__global__ void k_mtopk() {
    __shared__ float sv[256];
    __shared__ int   si[256];
    int row = blockIdx.x;
    int tid = threadIdx.x;
    sv[tid] = g_pv[row * 256 + tid];
    si[tid] = g_pi[row * 256 + tid];
    __syncthreads();
    for (int k = 2; k <= 256; k <<= 1) {
        for (int j = k >> 1; j > 0; j >>= 1) {
            int ixj = tid ^ j;
            if (ixj > tid) {
                float v1 = sv[tid], v2 = sv[ixj];
                int i1 = si[tid], i2 = si[ixj];
                bool desc = ((tid & k) == 0);
                bool sw = desc ? precede(v2, i2, v1, i1) : precede(v1, i1, v2, i2);
                if (sw) { sv[tid] = v2; si[tid] = i2; sv[ixj] = v1; si[ixj] = i1; }
            }
            __syncthreads();
        }
    }
    if (tid < TKP) g_ridx[row * TKP + tid] = si[tid];
}

// ---------------------------------------------------------------------------
// compensated-fp32 dot / dist2 (TwoProd via FMA + Neumaier; exact-class rank)
// ---------------------------------------------------------------------------
__device__ __forceinline__ double comp_dot(const float* __restrict__ a,
                                           const float* __restrict__ b, int lane) {
    float s = 0.f, comp = 0.f;
    for (int k = lane; k < D; k += 32) {
        float x = a[k], y = b[k];
        float p = x * y;
        float e = fmaf(x, y, -p);
        float t = s + p;
        comp += (fabsf(s) >= fabsf(p)) ? ((s - t) + p) : ((p - t) + s);
        s = t;
        comp += e;
    }
    return (double)s + (double)comp;
}

__device__ __forceinline__ double comp_dist2(const float* __restrict__ a,
                                             const float* __restrict__ b, int lane) {
    float s = 0.f, comp = 0.f;
    for (int k = lane; k < D; k += 32) {
        float d = a[k] - b[k];
        float p = d * d;
        float e = fmaf(d, d, -p);
        float t = s + p;
        comp += (fabsf(s) >= fabsf(p)) ? ((s - t) + p) : ((p - t) + s);
        s = t;
        comp += e;
    }
    return (double)s + (double)comp;
}

// ---------------------------------------------------------------------------
// refine top-32 sims -> exact top-16 (one block per anchor row)
// ---------------------------------------------------------------------------
__global__ __launch_bounds__(256)
void k_refine(const float* __restrict__ A, const float* __restrict__ Cand) {
    __shared__ double dv[TKP];
    __shared__ int    di[TKP];
    int row = blockIdx.x;
    int tid = threadIdx.x;
    int wid = tid >> 5, lane = tid & 31;
    const float* ar = A + (size_t)row * D;
    for (int c = wid; c < TKP; c += 8) {
        int idx = g_ridx[row * TKP + c];
        double s;
        if (idx >= 0 && idx < NC) {
            s = comp_dot(ar, Cand + (size_t)idx * D, lane);
        } else {
            s = (lane == 0) ? -CUDART_INF : 0.0;
        }
        #pragma unroll
        for (int o = 16; o; o >>= 1) s += __shfl_down_sync(0xffffffffu, s, o);
        if (lane == 0) { dv[c] = s; di[c] = idx; }
    }
    __syncthreads();
    if (tid == 0) {
        double tvv[TK]; int tii[TK]; int nf = 0;
        for (int s = 0; s < TKP; s++) {
            double v = dv[s]; int gi = di[s];
            if (nf == TK && !preceded(v, gi, tvv[TK - 1], tii[TK - 1])) continue;
            int p = (nf < TK) ? nf : TK - 1;
            while (p > 0 && preceded(v, gi, tvv[p - 1], tii[p - 1])) {
                tvv[p] = tvv[p - 1]; tii[p] = tii[p - 1]; p--;
            }
            tvv[p] = v; tii[p] = gi;
            if (nf < TK) nf++;
        }
        for (int k2 = 0; k2 < TK; k2++) g_fidx[row * TK + k2] = tii[k2];
    }
}

// ---------------------------------------------------------------------------
// refine 16 center candidates -> exact argmin + min_dist
// ---------------------------------------------------------------------------
__global__ __launch_bounds__(256)
void k_cenref(const float* __restrict__ A, const float* __restrict__ Cen,
              float* __restrict__ out) {
    __shared__ double dv[NSPLIT_C * 2];
    __shared__ int    di[NSPLIT_C * 2];
    int row = blockIdx.x;
    int tid = threadIdx.x;
    int wid = tid >> 5, lane = tid & 31;
    const float* ar = A + (size_t)row * D;
    for (int c = wid; c < NSPLIT_C * 2; c += 8) {
        int idx = g_cmi[row * NSPLIT_C * 2 + c];
        double s;
        if (idx >= 0 && idx < NCEN) {
            s = comp_dist2(ar, Cen + (size_t)idx * D, lane);
        } else {
            s = (lane == 0) ? CUDART_INF : 0.0;
        }
        #pragma unroll
        for (int o = 16; o; o >>= 1) s += __shfl_down_sync(0xffffffffu, s, o);
        if (lane == 0) { dv[c] = s; di[c] = idx; }
    }
    __syncthreads();
    if (tid == 0) {
        double best = CUDART_INF; int besti = 0x7fffffff;
        for (int s = 0; s < NSPLIT_C * 2; s++) {
            double v = dv[s]; int ii = di[s];
            if (v < best || (v == best && ii < besti)) { best = v; besti = ii; }
        }
        if (best < 0.0) best = 0.0;
        out[(size_t)NA * TK * D + row] = (float)besti;
        out[(size_t)NA * TK * D + NA + row] = (float)sqrt(best);
    }
}

// ---------------------------------------------------------------------------
// Gather: out[row][k][:] = candidates[idx][:]
// ---------------------------------------------------------------------------
__global__ void k_gather(const float* __restrict__ Cand, float* __restrict__ out) {
    int b = blockIdx.x;
    int t = threadIdx.x;
    int idx = g_fidx[b];
    const float4* c4 = (const float4*)(Cand + (size_t)idx * D);
    float4* o4 = (float4*)(out + (size_t)b * D);
    o4[t] = c4[t];
}

// ---------------------------------------------------------------------------
extern "C" void kernel_launch(void* const* d_in, const int* in_sizes, int n_in,
                              void* d_out, int out_size) {
    const float* A    = (const float*)d_in[0];   // anchors    [4096, 768]
    const float* Cand = (const float*)d_in[1];   // candidates [50000, 768]
    const float* Cen  = (const float*)d_in[2];   // centers    [10000, 768]
    float* out = (float*)d_out;

    // dynamic smem for k_topk
    int smem_topk = (2 * 64 * SAPAD + 2 * 128 * SBPAD) * 2          // bf16 tiles
                  + (2 * BM * TKP + 2 * BM * CAP + 3 * BM) * 4;     // topk state
    cudaFuncSetAttribute(k_topk, cudaFuncAttributeMaxDynamicSharedMemorySize, smem_topk);

    uint16_t *pAbf, *pCandbf, *pCenbf;
    cudaGetSymbolAddress((void**)&pAbf, g_Abf);
    cudaGetSymbolAddress((void**)&pCandbf, g_Candbf);
    cudaGetSymbolAddress((void**)&pCenbf, g_Cenbf);

    // launches 1-3: conversions to bf16
    k_cvt<<<(NA * D / 4 + 255) / 256, 256>>>((const float4*)A, (uint2*)pAbf, NA * D / 4);
    k_cvt<<<(NC * D / 4 + 255) / 256, 256>>>((const float4*)Cand, (uint2*)pCandbf, NC * D / 4);
    k_cvt<<<(NCEN * D / 4 + 255) / 256, 256>>>((const float4*)Cen, (uint2*)pCenbf, NCEN * D / 4);
    // launch 4 (ncu capture slot): candidates GEMM + top-32 pruning
    k_topk<<<dim3(NA / BM, NSPLIT), 256, smem_topk>>>();
    // ||center||^2, then centers GEMM + min-2 pruning
    k_c2<<<(NCEN * 32 + 255) / 256, 256>>>(Cen);
    k_centers<<<dim3(NA / BM, NSPLIT_C), 256>>>();
    // merge partials -> refine list
    k_mtopk<<<NA, 256>>>();
    // exact top-16 (compensated fp32)
    k_refine<<<NA, 256>>>(A, Cand);
    // exact argmin + min_dist
    k_cenref<<<NA, 256>>>(A, Cen, out);
    // gather hard negatives
    k_gather<<<NA * TK, 192>>>(Cand, out);
}

// round 15
// speedup vs baseline: 2.9052x; 1.0265x over previous
#include <cuda_runtime.h>
#include <cuda_fp16.h>
#include <math_constants.h>
#include <stdint.h>

// Problem constants
#define D      768
#define NA     4096
#define NC     50000
#define NCEN   10000
#define TK     16
#define TKP    32          // kept per split (slack for refine)

// splits
#define NSPLIT   8
#define CHUNK    (NC / NSPLIT)        // 6250
#define NSPLIT_C 8
#define CHUNK_C  (NCEN / NSPLIT_C)    // 1250

// MMA tiling (fp16 in / fp16 accum, m16n8k16) — R13 skeleton
#define BM 64
#define BN 128
#define BK 32
#define NKC (D / BK)       // 24 k-chunks
#define SAPAD 40           // fp16 elems per smem row (80B stride)
#define SBPAD 40

#define CAP 128            // per-tile append buffer = BN (cannot overflow)

// ---- scratch (static __device__ globals) ----
__device__ __align__(16) uint16_t g_Ah[NA * D];
__device__ __align__(16) uint16_t g_Candh[(size_t)NC * D];
__device__ __align__(16) uint16_t g_Cenh[NCEN * D];

__device__ float g_pv[NA * NSPLIT * TKP];
__device__ int   g_pi[NA * NSPLIT * TKP];
__device__ int   g_ridx[NA * TKP];
__device__ float g_cmv[NA * NSPLIT_C * 2];
__device__ int   g_cmi[NA * NSPLIT_C * 2];
__device__ float g_c2[NCEN];
__device__ int   g_fidx[NA * TK];

__device__ __forceinline__ bool precede(float v1, int i1, float v2, int i2) {
    return (v1 > v2) || (v1 == v2 && i1 < i2);
}
__device__ __forceinline__ bool preceded(double v1, int i1, double v2, int i2) {
    return (v1 > v2) || (v1 == v2 && i1 < i2);
}

// m16n8k16, f16 inputs, f16 accumulators (D packed as 2 x f16x2)
__device__ __forceinline__ void mma16816h(uint32_t* c, const uint32_t* a, const uint32_t* b) {
    asm volatile(
        "mma.sync.aligned.m16n8k16.row.col.f16.f16.f16.f16 "
        "{%0,%1}, {%2,%3,%4,%5}, {%6,%7}, {%0,%1};"
        : "+r"(c[0]), "+r"(c[1])
        : "r"(a[0]), "r"(a[1]), "r"(a[2]), "r"(a[3]), "r"(b[0]), "r"(b[1]));
}
__device__ __forceinline__ void cp16(uint32_t dst, const void* src, int sz) {
    asm volatile("cp.async.cg.shared.global [%0], [%1], 16, %2;"
                 :: "r"(dst), "l"(src), "r"(sz) : "memory");
}
__device__ __forceinline__ void cp_commit() {
    asm volatile("cp.async.commit_group;" ::: "memory");
}

// ---------------------------------------------------------------------------
// float -> fp16 conversion (vectorized)
// ---------------------------------------------------------------------------
__global__ void k_cvt(const float4* __restrict__ s, uint2* __restrict__ d, int n4) {
    int i = blockIdx.x * blockDim.x + threadIdx.x;
    if (i >= n4) return;
    float4 v = s[i];
    __half2 p0 = __floats2half2_rn(v.x, v.y);
    __half2 p1 = __floats2half2_rn(v.z, v.w);
    uint2 o;
    o.x = *(uint32_t*)&p0;
    o.y = *(uint32_t*)&p1;
    d[i] = o;
}

// ---------------------------------------------------------------------------
// ||center||^2 precompute (fp32, pruning only)
// ---------------------------------------------------------------------------
__global__ void k_c2(const float* __restrict__ cen) {
    int w = (blockIdx.x * blockDim.x + threadIdx.x) >> 5;
    int lane = threadIdx.x & 31;
    if (w >= NCEN) return;
    const float* p = cen + (size_t)w * D;
    float s = 0.f;
    for (int k = lane; k < D; k += 32) { float x = p[k]; s += x * x; }
    #pragma unroll
    for (int o = 16; o; o >>= 1) s += __shfl_down_sync(0xffffffffu, s, o);
    if (lane == 0) g_c2[w] = s;
}

// ---------------------------------------------------------------------------
// fp16 MMA GEMM + fused per-row top-32 (partial over a column chunk)
// grid (NA/BM, NSPLIT), 256 threads, dynamic smem
// ---------------------------------------------------------------------------
extern __shared__ __align__(16) char smraw[];

__global__ __launch_bounds__(256)
void k_topk(void) {
    uint16_t* As = (uint16_t*)smraw;                     // [2][64*SAPAD]
    uint16_t* Bs = As + 2 * 64 * SAPAD;                  // [2][128*SBPAD]
    float* topv   = (float*)(Bs + 2 * 128 * SBPAD);      // [BM][TKP]
    int*   topi   = (int*)(topv + BM * TKP);
    float* bufv   = (float*)(topi + BM * TKP);           // [BM][CAP]
    int*   bufi   = (int*)(bufv + BM * CAP);
    float* thresh = (float*)(bufi + BM * CAP);           // [BM]
    int*   cnt    = (int*)(thresh + BM);
    int*   nfill  = cnt + BM;

    int tid = threadIdx.x;
    int lane = tid & 31, wid = tid >> 5;
    int gid = lane >> 2, tig = lane & 3;
    int wm = wid & 1, wn = wid >> 1;     // warp covers rows wm*32.., cols wn*32..
    int ar = tid >> 2, aq = tid & 3;     // loader mapping

    int rowBase = blockIdx.x * BM;
    int split = blockIdx.y;
    int colStart = split * CHUNK;
    int colEnd = colStart + CHUNK;

    if (tid < BM) { thresh[tid] = -CUDART_INF_F; cnt[tid] = 0; nfill[tid] = 0; }
    __syncthreads();

    uint32_t sA = (uint32_t)__cvta_generic_to_shared(As);
    uint32_t sB = (uint32_t)__cvta_generic_to_shared(Bs);

    int nT = (CHUNK + BN - 1) / BN;
    for (int t = 0; t < nT; t++) {
        int colBase = colStart + t * BN;
        uint32_t c[2][4][2];                 // f16x2 accumulators
        #pragma unroll
        for (int i = 0; i < 2; i++)
            #pragma unroll
            for (int j = 0; j < 4; j++) { c[i][j][0] = 0u; c[i][j][1] = 0u; }

        auto issueAB = [&](int st, int kt) {
            uint32_t dstA = sA + (uint32_t)(st * 64 * SAPAD + ar * SAPAD + aq * 8) * 2;
            const uint16_t* srcA = g_Ah + (size_t)(rowBase + ar) * D + kt + aq * 8;
            cp16(dstA, srcA, 16);
            #pragma unroll
            for (int h = 0; h < 2; h++) {
                int r = ar + h * 64;
                int gc = colBase + r;
                bool ok = gc < colEnd;
                uint32_t dstB = sB + (uint32_t)(st * 128 * SBPAD + r * SBPAD + aq * 8) * 2;
                const uint16_t* srcB = g_Candh + (size_t)(ok ? gc : 0) * D + kt + aq * 8;
                cp16(dstB, srcB, ok ? 16 : 0);
            }
            cp_commit();
        };

        issueAB(0, 0);
        for (int kk = 0; kk < NKC; kk++) {
            int cur = kk & 1;
            if (kk + 1 < NKC) {
                issueAB((kk + 1) & 1, (kk + 1) * BK);
                asm volatile("cp.async.wait_group 1;" ::: "memory");
            } else {
                asm volatile("cp.async.wait_group 0;" ::: "memory");
            }
            __syncthreads();
            const uint16_t* Ab = As + cur * 64 * SAPAD;
            const uint16_t* Bb = Bs + cur * 128 * SBPAD;
            #pragma unroll
            for (int ks = 0; ks < 2; ks++) {
                int k0 = ks * 16;
                uint32_t af[2][4], fb[4][2];
                #pragma unroll
                for (int i = 0; i < 2; i++) {
                    int r = wm * 32 + i * 16 + gid;
                    af[i][0] = *(const uint32_t*)(Ab + r * SAPAD + k0 + 2 * tig);
                    af[i][1] = *(const uint32_t*)(Ab + (r + 8) * SAPAD + k0 + 2 * tig);
                    af[i][2] = *(const uint32_t*)(Ab + r * SAPAD + k0 + 8 + 2 * tig);
                    af[i][3] = *(const uint32_t*)(Ab + (r + 8) * SAPAD + k0 + 8 + 2 * tig);
                }
                #pragma unroll
                for (int j = 0; j < 4; j++) {
                    int n = wn * 32 + j * 8 + gid;
                    fb[j][0] = *(const uint32_t*)(Bb + n * SBPAD + k0 + 2 * tig);
                    fb[j][1] = *(const uint32_t*)(Bb + n * SBPAD + k0 + 8 + 2 * tig);
                }
                #pragma unroll
                for (int i = 0; i < 2; i++)
                    #pragma unroll
                    for (int j = 0; j < 4; j++)
                        mma16816h(c[i][j], af[i], fb[j]);
            }
            __syncthreads();
        }

        // ---- epilogue: unpack f16 accums, append above-threshold candidates ----
        float th[4];
        #pragma unroll
        for (int i = 0; i < 2; i++)
            #pragma unroll
            for (int hi = 0; hi < 2; hi++)
                th[i * 2 + hi] = thresh[wm * 32 + i * 16 + hi * 8 + gid];

        #pragma unroll
        for (int i = 0; i < 2; i++) {
            #pragma unroll
            for (int hi = 0; hi < 2; hi++) {      // hi: 0 -> row r, 1 -> row r+8
                int lr = wm * 32 + i * 16 + hi * 8 + gid;
                int grow = rowBase + lr;
                float thv = th[i * 2 + hi];
                #pragma unroll
                for (int j = 0; j < 4; j++) {
                    float2 vv = __half22float2(*(__half2*)&c[i][j][hi]);
                    #pragma unroll
                    for (int e = 0; e < 2; e++) {
                        int gc = colBase + wn * 32 + j * 8 + 2 * tig + e;
                        float v = (e == 0) ? vv.x : vv.y;
                        if (gc < colEnd && gc != grow && v > thv) {
                            int slot = atomicAdd(&cnt[lr], 1);
                            if (slot < CAP) { bufv[lr * CAP + slot] = v; bufi[lr * CAP + slot] = gc; }
                        }
                    }
                }
            }
        }
        __syncthreads();
        // ---- compaction: one thread per row ----
        if (tid < BM) {
            int cc = cnt[tid];
            if (cc > 0) {
                if (cc > CAP) cc = CAP;
                int nf = nfill[tid];
                float* tv = topv + tid * TKP;
                int*   ti = topi + tid * TKP;
                for (int s = 0; s < cc; s++) {
                    float v = bufv[tid * CAP + s];
                    int gi = bufi[tid * CAP + s];
                    if (nf == TKP && !precede(v, gi, tv[TKP - 1], ti[TKP - 1])) continue;
                    int p = (nf < TKP) ? nf : TKP - 1;
                    while (p > 0 && precede(v, gi, tv[p - 1], ti[p - 1])) {
                        tv[p] = tv[p - 1]; ti[p] = ti[p - 1]; p--;
                    }
                    tv[p] = v; ti[p] = gi;
                    if (nf < TKP) nf++;
                }
                nfill[tid] = nf;
                cnt[tid] = 0;
                if (nf == TKP) thresh[tid] = tv[TKP - 1];
            }
        }
        __syncthreads();
    }
    if (tid < BM) {
        int row = rowBase + tid;
        int nf = nfill[tid];
        for (int k2 = 0; k2 < TKP; k2++) {
            g_pv[(row * NSPLIT + split) * TKP + k2] = (k2 < nf) ? topv[tid * TKP + k2] : -CUDART_INF_F;
            g_pi[(row * NSPLIT + split) * TKP + k2] = (k2 < nf) ? topi[tid * TKP + k2] : 0x7fffffff;
        }
    }
}

// ---------------------------------------------------------------------------
// fp16 MMA centers GEMM + fused min-2 of (c2 - 2*dot) per split
// grid (NA/BM, NSPLIT_C), 256 threads, static smem
// ---------------------------------------------------------------------------
__global__ __launch_bounds__(256)
void k_centers(void) {
    __shared__ __align__(16) uint16_t As[2 * 64 * SAPAD];
    __shared__ __align__(16) uint16_t Bs[2 * 128 * SBPAD];
    __shared__ float redv[BM * 32];
    __shared__ int   redi[BM * 32];

    int tid = threadIdx.x;
    int lane = tid & 31, wid = tid >> 5;
    int gid = lane >> 2, tig = lane & 3;
    int wm = wid & 1, wn = wid >> 1;
    int ar = tid >> 2, aq = tid & 3;

    int rowBase = blockIdx.x * BM;
    int split = blockIdx.y;
    int colStart = split * CHUNK_C;
    int colEnd = colStart + CHUNK_C;

    uint32_t sA = (uint32_t)__cvta_generic_to_shared(As);
    uint32_t sB = (uint32_t)__cvta_generic_to_shared(Bs);

    float bv0[4], bv1[4]; int bi0[4], bi1[4];
    #pragma unroll
    for (int i = 0; i < 4; i++) {
        bv0[i] = bv1[i] = CUDART_INF_F;
        bi0[i] = bi1[i] = 0x7fffffff;
    }

    int nT = (CHUNK_C + BN - 1) / BN;
    for (int t = 0; t < nT; t++) {
        int colBase = colStart + t * BN;
        uint32_t c[2][4][2];
        #pragma unroll
        for (int i = 0; i < 2; i++)
            #pragma unroll
            for (int j = 0; j < 4; j++) { c[i][j][0] = 0u; c[i][j][1] = 0u; }

        auto issueAB = [&](int st, int kt) {
            uint32_t dstA = sA + (uint32_t)(st * 64 * SAPAD + ar * SAPAD + aq * 8) * 2;
            const uint16_t* srcA = g_Ah + (size_t)(rowBase + ar) * D + kt + aq * 8;
            cp16(dstA, srcA, 16);
            #pragma unroll
            for (int h = 0; h < 2; h++) {
                int r = ar + h * 64;
                int gc = colBase + r;
                bool ok = gc < colEnd;
                uint32_t dstB = sB + (uint32_t)(st * 128 * SBPAD + r * SBPAD + aq * 8) * 2;
                const uint16_t* srcB = g_Cenh + (size_t)(ok ? gc : 0) * D + kt + aq * 8;
                cp16(dstB, srcB, ok ? 16 : 0);
            }
            cp_commit();
        };

        issueAB(0, 0);
        for (int kk = 0; kk < NKC; kk++) {
            int cur = kk & 1;
            if (kk + 1 < NKC) {
                issueAB((kk + 1) & 1, (kk + 1) * BK);
                asm volatile("cp.async.wait_group 1;" ::: "memory");
            } else {
                asm volatile("cp.async.wait_group 0;" ::: "memory");
            }
            __syncthreads();
            const uint16_t* Ab = As + cur * 64 * SAPAD;
            const uint16_t* Bb = Bs + cur * 128 * SBPAD;
            #pragma unroll
            for (int ks = 0; ks < 2; ks++) {
                int k0 = ks * 16;
                uint32_t af[2][4], fb[4][2];
                #pragma unroll
                for (int i = 0; i < 2; i++) {
                    int r = wm * 32 + i * 16 + gid;
                    af[i][0] = *(const uint32_t*)(Ab + r * SAPAD + k0 + 2 * tig);
                    af[i][1] = *(const uint32_t*)(Ab + (r + 8) * SAPAD + k0 + 2 * tig);
                    af[i][2] = *(const uint32_t*)(Ab + r * SAPAD + k0 + 8 + 2 * tig);
                    af[i][3] = *(const uint32_t*)(Ab + (r + 8) * SAPAD + k0 + 8 + 2 * tig);
                }
                #pragma unroll
                for (int j = 0; j < 4; j++) {
                    int n = wn * 32 + j * 8 + gid;
                    fb[j][0] = *(const uint32_t*)(Bb + n * SBPAD + k0 + 2 * tig);
                    fb[j][1] = *(const uint32_t*)(Bb + n * SBPAD + k0 + 8 + 2 * tig);
                }
                #pragma unroll
                for (int i = 0; i < 2; i++)
                    #pragma unroll
                    for (int j = 0; j < 4; j++)
                        mma16816h(c[i][j], af[i], fb[j]);
            }
            __syncthreads();
        }

        // min-2 update (unpack f16 accums)
        #pragma unroll
        for (int i = 0; i < 2; i++)
            #pragma unroll
            for (int hi = 0; hi < 2; hi++) {
                int ri = i * 2 + hi;
                #pragma unroll
                for (int j = 0; j < 4; j++) {
                    float2 vv = __half22float2(*(__half2*)&c[i][j][hi]);
                    #pragma unroll
                    for (int e = 0; e < 2; e++) {
                        int gc = colBase + wn * 32 + j * 8 + 2 * tig + e;
                        if (gc < colEnd) {
                            float dotv = (e == 0) ? vv.x : vv.y;
                            float v = g_c2[gc] - 2.0f * dotv;
                            if (v < bv0[ri] || (v == bv0[ri] && gc < bi0[ri])) {
                                bv1[ri] = bv0[ri]; bi1[ri] = bi0[ri];
                                bv0[ri] = v; bi0[ri] = gc;
                            } else if (v < bv1[ri] || (v == bv1[ri] && gc < bi1[ri])) {
                                bv1[ri] = v; bi1[ri] = gc;
                            }
                        }
                    }
                }
            }
    }

    // reduction across the 16 thread-columns holding each row
    int sid = wn * 4 + tig;   // 0..15
    #pragma unroll
    for (int i = 0; i < 2; i++)
        #pragma unroll
        for (int hi = 0; hi < 2; hi++) {
            int ri = i * 2 + hi;
            int lr = wm * 32 + i * 16 + hi * 8 + gid;
            redv[lr * 32 + sid * 2 + 0] = bv0[ri];
            redi[lr * 32 + sid * 2 + 0] = bi0[ri];
            redv[lr * 32 + sid * 2 + 1] = bv1[ri];
            redi[lr * 32 + sid * 2 + 1] = bi1[ri];
        }
    __syncthreads();
    if (tid < BM) {
        float b0 = CUDART_INF_F, b1 = CUDART_INF_F;
        int i0 = 0x7fffffff, i1 = 0x7fffffff;
        for (int x = 0; x < 32; x++) {
            float v = redv[tid * 32 + x]; int ii = redi[tid * 32 + x];
            if (v < b0 || (v == b0 && ii < i0)) { b1 = b0; i1 = i0; b0 = v; i0 = ii; }
            else if (v < b1 || (v == b1 && ii < i1)) { b1 = v; i1 = ii; }
        }
        int row = rowBase + tid;
        g_cmv[(row * NSPLIT_C + split) * 2 + 0] = b0;
        g_cmi[(row * NSPLIT_C + split) * 2 + 0] = i0;
        g_cmv[(row * NSPLIT_C + split) * 2 + 1] = b1;
        g_cmi[(row * NSPLIT_C + split) * 2 + 1] = i1;
    }
}

// ---------------------------------------------------------------------------
// Merge topk partials: bitonic sort of 256 pairs/row, keep top-32
// ---------------------------------------------------------------------------
__global__ void k_mtopk() {
    __shared__ float sv[256];
    __shared__ int   si[256];
    int row = blockIdx.x;
    int tid = threadIdx.x;
    sv[tid] = g_pv[row * 256 + tid];
    si[tid] = g_pi[row * 256 + tid];
    __syncthreads();
    for (int k = 2; k <= 256; k <<= 1) {
        for (int j = k >> 1; j > 0; j >>= 1) {
            int ixj = tid ^ j;
            if (ixj > tid) {
                float v1 = sv[tid], v2 = sv[ixj];
                int i1 = si[tid], i2 = si[ixj];
                bool desc = ((tid & k) == 0);
                bool sw = desc ? precede(v2, i2, v1, i1) : precede(v1, i1, v2, i2);
                if (sw) { sv[tid] = v2; si[tid] = i2; sv[ixj] = v1; si[ixj] = i1; }
            }
            __syncthreads();
        }
    }
    if (tid < TKP) g_ridx[row * TKP + tid] = si[tid];
}

// ---------------------------------------------------------------------------
// compensated-fp32 dot / dist2 (TwoProd via FMA + Neumaier; exact-class rank)
// ---------------------------------------------------------------------------
__device__ __forceinline__ double comp_dot(const float* __restrict__ a,
                                           const float* __restrict__ b, int lane) {
    float s = 0.f, comp = 0.f;
    for (int k = lane; k < D; k += 32) {
        float x = a[k], y = b[k];
        float p = x * y;
        float e = fmaf(x, y, -p);
        float t = s + p;
        comp += (fabsf(s) >= fabsf(p)) ? ((s - t) + p) : ((p - t) + s);
        s = t;
        comp += e;
    }
    return (double)s + (double)comp;
}

__device__ __forceinline__ double comp_dist2(const float* __restrict__ a,
                                             const float* __restrict__ b, int lane) {
    float s = 0.f, comp = 0.f;
    for (int k = lane; k < D; k += 32) {
        float d = a[k] - b[k];
        float p = d * d;
        float e = fmaf(d, d, -p);
        float t = s + p;
        comp += (fabsf(s) >= fabsf(p)) ? ((s - t) + p) : ((p - t) + s);
        s = t;
        comp += e;
    }
    return (double)s + (double)comp;
}

// ---------------------------------------------------------------------------
// refine top-32 sims -> exact top-16 (one block per anchor row)
// ---------------------------------------------------------------------------
__global__ __launch_bounds__(256)
void k_refine(const float* __restrict__ A, const float* __restrict__ Cand) {
    __shared__ double dv[TKP];
    __shared__ int    di[TKP];
    int row = blockIdx.x;
    int tid = threadIdx.x;
    int wid = tid >> 5, lane = tid & 31;
    const float* ar = A + (size_t)row * D;
    for (int c = wid; c < TKP; c += 8) {
        int idx = g_ridx[row * TKP + c];
        double s;
        if (idx >= 0 && idx < NC) {
            s = comp_dot(ar, Cand + (size_t)idx * D, lane);
        } else {
            s = (lane == 0) ? -CUDART_INF : 0.0;
        }
        #pragma unroll
        for (int o = 16; o; o >>= 1) s += __shfl_down_sync(0xffffffffu, s, o);
        if (lane == 0) { dv[c] = s; di[c] = idx; }
    }
    __syncthreads();
    if (tid == 0) {
        double tvv[TK]; int tii[TK]; int nf = 0;
        for (int s = 0; s < TKP; s++) {
            double v = dv[s]; int gi = di[s];
            if (nf == TK && !preceded(v, gi, tvv[TK - 1], tii[TK - 1])) continue;
            int p = (nf < TK) ? nf : TK - 1;
            while (p > 0 && preceded(v, gi, tvv[p - 1], tii[p - 1])) {
                tvv[p] = tvv[p - 1]; tii[p] = tii[p - 1]; p--;
            }
            tvv[p] = v; tii[p] = gi;
            if (nf < TK) nf++;
        }
        for (int k2 = 0; k2 < TK; k2++) g_fidx[row * TK + k2] = tii[k2];
    }
}

// ---------------------------------------------------------------------------
// refine 16 center candidates -> exact argmin + min_dist
// ---------------------------------------------------------------------------
__global__ __launch_bounds__(256)
void k_cenref(const float* __restrict__ A, const float* __restrict__ Cen,
              float* __restrict__ out) {
    __shared__ double dv[NSPLIT_C * 2];
    __shared__ int    di[NSPLIT_C * 2];
    int row = blockIdx.x;
    int tid = threadIdx.x;
    int wid = tid >> 5, lane = tid & 31;
    const float* ar = A + (size_t)row * D;
    for (int c = wid; c < NSPLIT_C * 2; c += 8) {
        int idx = g_cmi[row * NSPLIT_C * 2 + c];
        double s;
        if (idx >= 0 && idx < NCEN) {
            s = comp_dist2(ar, Cen + (size_t)idx * D, lane);
        } else {
            s = (lane == 0) ? CUDART_INF : 0.0;
        }
        #pragma unroll
        for (int o = 16; o; o >>= 1) s += __shfl_down_sync(0xffffffffu, s, o);
        if (lane == 0) { dv[c] = s; di[c] = idx; }
    }
    __syncthreads();
    if (tid == 0) {
        double best = CUDART_INF; int besti = 0x7fffffff;
        for (int s = 0; s < NSPLIT_C * 2; s++) {
            double v = dv[s]; int ii = di[s];
            if (v < best || (v == best && ii < besti)) { best = v; besti = ii; }
        }
        if (best < 0.0) best = 0.0;
        out[(size_t)NA * TK * D + row] = (float)besti;
        out[(size_t)NA * TK * D + NA + row] = (float)sqrt(best);
    }
}

// ---------------------------------------------------------------------------
// Gather: out[row][k][:] = candidates[idx][:]
// ---------------------------------------------------------------------------
__global__ void k_gather(const float* __restrict__ Cand, float* __restrict__ out) {
    int b = blockIdx.x;
    int t = threadIdx.x;
    int idx = g_fidx[b];
    const float4* c4 = (const float4*)(Cand + (size_t)idx * D);
    float4* o4 = (float4*)(out + (size_t)b * D);
    o4[t] = c4[t];
}

// ---------------------------------------------------------------------------
extern "C" void kernel_launch(void* const* d_in, const int* in_sizes, int n_in,
                              void* d_out, int out_size) {
    const float* A    = (const float*)d_in[0];   // anchors    [4096, 768]
    const float* Cand = (const float*)d_in[1];   // candidates [50000, 768]
    const float* Cen  = (const float*)d_in[2];   // centers    [10000, 768]
    float* out = (float*)d_out;

    // dynamic smem for k_topk
    int smem_topk = (2 * 64 * SAPAD + 2 * 128 * SBPAD) * 2          // fp16 tiles
                  + (2 * BM * TKP + 2 * BM * CAP + 3 * BM) * 4;     // topk state
    cudaFuncSetAttribute(k_topk, cudaFuncAttributeMaxDynamicSharedMemorySize, smem_topk);

    uint16_t *pAh, *pCandh, *pCenh;
    cudaGetSymbolAddress((void**)&pAh, g_Ah);
    cudaGetSymbolAddress((void**)&pCandh, g_Candh);
    cudaGetSymbolAddress((void**)&pCenh, g_Cenh);

    // launches 1-3: conversions to fp16
    k_cvt<<<(NA * D / 4 + 255) / 256, 256>>>((const float4*)A, (uint2*)pAh, NA * D / 4);
    k_cvt<<<(NC * D / 4 + 255) / 256, 256>>>((const float4*)Cand, (uint2*)pCandh, NC * D / 4);
    k_cvt<<<(NCEN * D / 4 + 255) / 256, 256>>>((const float4*)Cen, (uint2*)pCenh, NCEN * D / 4);
    // launch 4 (ncu capture slot): candidates GEMM + top-32 pruning
    k_topk<<<dim3(NA / BM, NSPLIT), 256, smem_topk>>>();
    // ||center||^2, then centers GEMM + min-2 pruning
    k_c2<<<(NCEN * 32 + 255) / 256, 256>>>(Cen);
    k_centers<<<dim3(NA / BM, NSPLIT_C), 256>>>();
    // merge partials -> refine list
    k_mtopk<<<NA, 256>>>();
    // exact top-16 (compensated fp32)
    k_refine<<<NA, 256>>>(A, Cand);
    // exact argmin + min_dist
    k_cenref<<<NA, 256>>>(A, Cen, out);
    // gather hard negatives
    k_gather<<<NA * TK, 192>>>(Cand, out);
}

// round 17
// speedup vs baseline: 2.9271x; 1.0075x over previous
#include <cuda_runtime.h>
#include <cuda_fp16.h>
#include <math_constants.h>
#include <stdint.h>

// Problem constants
#define D      768
#define NA     4096
#define NC     50000
#define NCEN   10000
#define TK     16
#define TKP    32          // kept per split (slack for refine)

// splits
#define NSPLIT   8
#define CHUNK    (NC / NSPLIT)        // 6250
#define NSPLIT_C 8
#define CHUNK_C  (NCEN / NSPLIT_C)    // 1250

// MMA tiling (fp16 in / fp16 accum, m16n8k16)
#define BM 64
#define BN 128
#define BK 32
#define NKC (D / BK)       // 24 k-chunks
#define SAPAD 40           // fp16 elems per smem row (80B stride, LDSM-conflict-free)
#define SBPAD 40

#define CAP 128            // per-tile append buffer = BN (cannot overflow)

// ---- scratch (static __device__ globals) ----
__device__ __align__(16) uint16_t g_Ah[NA * D];
__device__ __align__(16) uint16_t g_Candh[(size_t)NC * D];
__device__ __align__(16) uint16_t g_Cenh[NCEN * D];

__device__ float g_pv[NA * NSPLIT * TKP];
__device__ int   g_pi[NA * NSPLIT * TKP];
__device__ int   g_ridx[NA * TKP];
__device__ float g_cmv[NA * NSPLIT_C * 2];
__device__ int   g_cmi[NA * NSPLIT_C * 2];
__device__ float g_c2[NCEN];
__device__ int   g_fidx[NA * TK];

__device__ __forceinline__ bool precede(float v1, int i1, float v2, int i2) {
    return (v1 > v2) || (v1 == v2 && i1 < i2);
}
__device__ __forceinline__ bool preceded(double v1, int i1, double v2, int i2) {
    return (v1 > v2) || (v1 == v2 && i1 < i2);
}

// m16n8k16, f16 inputs, f16 accumulators (D packed as 2 x f16x2)
__device__ __forceinline__ void mma16816h(uint32_t* c, const uint32_t* a, const uint32_t* b) {
    asm volatile(
        "mma.sync.aligned.m16n8k16.row.col.f16.f16.f16.f16 "
        "{%0,%1}, {%2,%3,%4,%5}, {%6,%7}, {%0,%1};"
        : "+r"(c[0]), "+r"(c[1])
        : "r"(a[0]), "r"(a[1]), "r"(a[2]), "r"(a[3]), "r"(b[0]), "r"(b[1]));
}
__device__ __forceinline__ void ldsm_x4(uint32_t* r, uint32_t addr) {
    asm volatile("ldmatrix.sync.aligned.m8n8.x4.shared.b16 {%0,%1,%2,%3}, [%4];"
                 : "=r"(r[0]), "=r"(r[1]), "=r"(r[2]), "=r"(r[3]) : "r"(addr));
}
__device__ __forceinline__ void cp16(uint32_t dst, const void* src, int sz) {
    asm volatile("cp.async.cg.shared.global [%0], [%1], 16, %2;"
                 :: "r"(dst), "l"(src), "r"(sz) : "memory");
}
__device__ __forceinline__ void cp_commit() {
    asm volatile("cp.async.commit_group;" ::: "memory");
}

// ---------------------------------------------------------------------------
// float -> fp16 conversion (vectorized)
// ---------------------------------------------------------------------------
__global__ void k_cvt(const float4* __restrict__ s, uint2* __restrict__ d, int n4) {
    int i = blockIdx.x * blockDim.x + threadIdx.x;
    if (i >= n4) return;
    float4 v = s[i];
    __half2 p0 = __floats2half2_rn(v.x, v.y);
    __half2 p1 = __floats2half2_rn(v.z, v.w);
    uint2 o;
    o.x = *(uint32_t*)&p0;
    o.y = *(uint32_t*)&p1;
    d[i] = o;
}

// ---------------------------------------------------------------------------
// ||center||^2 precompute (fp32, pruning only)
// ---------------------------------------------------------------------------
__global__ void k_c2(const float* __restrict__ cen) {
    int w = (blockIdx.x * blockDim.x + threadIdx.x) >> 5;
    int lane = threadIdx.x & 31;
    if (w >= NCEN) return;
    const float* p = cen + (size_t)w * D;
    float s = 0.f;
    for (int k = lane; k < D; k += 32) { float x = p[k]; s += x * x; }
    #pragma unroll
    for (int o = 16; o; o >>= 1) s += __shfl_down_sync(0xffffffffu, s, o);
    if (lane == 0) g_c2[w] = s;
}

// ---------------------------------------------------------------------------
// fp16 MMA GEMM + fused per-row top-32 (partial over a column chunk)
// grid (NA/BM, NSPLIT), 256 threads, dynamic smem
// ---------------------------------------------------------------------------
extern __shared__ __align__(16) char smraw[];

__global__ __launch_bounds__(256)
void k_topk(void) {
    uint16_t* As = (uint16_t*)smraw;                     // [2][64*SAPAD]
    uint16_t* Bs = As + 2 * 64 * SAPAD;                  // [2][128*SBPAD]
    float* topv   = (float*)(Bs + 2 * 128 * SBPAD);      // [BM][TKP]
    int*   topi   = (int*)(topv + BM * TKP);
    float* bufv   = (float*)(topi + BM * TKP);           // [BM][CAP]
    int*   bufi   = (int*)(bufv + BM * CAP);
    float* thresh = (float*)(bufi + BM * CAP);           // [BM]
    int*   cnt    = (int*)(thresh + BM);
    int*   nfill  = cnt + BM;

    int tid = threadIdx.x;
    int lane = tid & 31, wid = tid >> 5;
    int gid = lane >> 2, tig = lane & 3;
    int wm = wid & 1, wn = wid >> 1;     // warp covers rows wm*32.., cols wn*32..
    int ar = tid >> 2, aq = tid & 3;     // loader mapping

    // ldmatrix per-lane addressing (validated against scalar-load layout)
    int aRow0 = (lane & 7) + ((lane >> 3) & 1) * 8;   // row-in-16 for A matrices
    int aKsel = (lane >> 4) * 8;                      // k half-select for A
    int bRow0 = (lane & 7) + ((lane >> 3) >> 1) * 8;  // n-in-16 for B matrix pair
    int bKsel = ((lane >> 3) & 1) * 8;                // k half-select for B

    int rowBase = blockIdx.x * BM;
    int split = blockIdx.y;
    int colStart = split * CHUNK;
    int colEnd = colStart + CHUNK;

    if (tid < BM) { thresh[tid] = -CUDART_INF_F; cnt[tid] = 0; nfill[tid] = 0; }
    __syncthreads();

    uint32_t sA = (uint32_t)__cvta_generic_to_shared(As);
    uint32_t sB = (uint32_t)__cvta_generic_to_shared(Bs);

    int nT = (CHUNK + BN - 1) / BN;
    for (int t = 0; t < nT; t++) {
        int colBase = colStart + t * BN;
        uint32_t c[2][4][2];                 // f16x2 accumulators
        #pragma unroll
        for (int i = 0; i < 2; i++)
            #pragma unroll
            for (int j = 0; j < 4; j++) { c[i][j][0] = 0u; c[i][j][1] = 0u; }

        auto issueAB = [&](int st, int kt) {
            uint32_t dstA = sA + (uint32_t)(st * 64 * SAPAD + ar * SAPAD + aq * 8) * 2;
            const uint16_t* srcA = g_Ah + (size_t)(rowBase + ar) * D + kt + aq * 8;
            cp16(dstA, srcA, 16);
            #pragma unroll
            for (int h = 0; h < 2; h++) {
                int r = ar + h * 64;
                int gc = colBase + r;
                bool ok = gc < colEnd;
                uint32_t dstB = sB + (uint32_t)(st * 128 * SBPAD + r * SBPAD + aq * 8) * 2;
                const uint16_t* srcB = g_Candh + (size_t)(ok ? gc : 0) * D + kt + aq * 8;
                cp16(dstB, srcB, ok ? 16 : 0);
            }
            cp_commit();
        };

        issueAB(0, 0);
        for (int kk = 0; kk < NKC; kk++) {
            int cur = kk & 1;
            if (kk + 1 < NKC) {
                issueAB((kk + 1) & 1, (kk + 1) * BK);
                asm volatile("cp.async.wait_group 1;" ::: "memory");
            } else {
                asm volatile("cp.async.wait_group 0;" ::: "memory");
            }
            __syncthreads();
            uint32_t sAc = sA + (uint32_t)(cur * 64 * SAPAD) * 2;
            uint32_t sBc = sB + (uint32_t)(cur * 128 * SBPAD) * 2;
            #pragma unroll
            for (int ks = 0; ks < 2; ks++) {
                int k0 = ks * 16;
                uint32_t af[2][4], fb[4][2];
                #pragma unroll
                for (int i = 0; i < 2; i++)
                    ldsm_x4(af[i], sAc + (uint32_t)((wm * 32 + i * 16 + aRow0) * SAPAD
                                                    + k0 + aKsel) * 2);
                #pragma unroll
                for (int jp = 0; jp < 2; jp++) {
                    uint32_t tmp[4];
                    ldsm_x4(tmp, sBc + (uint32_t)((wn * 32 + jp * 16 + bRow0) * SBPAD
                                                  + k0 + bKsel) * 2);
                    fb[2 * jp][0] = tmp[0]; fb[2 * jp][1] = tmp[1];
                    fb[2 * jp + 1][0] = tmp[2]; fb[2 * jp + 1][1] = tmp[3];
                }
                #pragma unroll
                for (int i = 0; i < 2; i++)
                    #pragma unroll
                    for (int j = 0; j < 4; j++)
                        mma16816h(c[i][j], af[i], fb[j]);
            }
            __syncthreads();
        }

        // ---- epilogue: unpack f16 accums, append above-threshold candidates ----
        float th[4];
        #pragma unroll
        for (int i = 0; i < 2; i++)
            #pragma unroll
            for (int hi = 0; hi < 2; hi++)
                th[i * 2 + hi] = thresh[wm * 32 + i * 16 + hi * 8 + gid];

        #pragma unroll
        for (int i = 0; i < 2; i++) {
            #pragma unroll
            for (int hi = 0; hi < 2; hi++) {      // hi: 0 -> row r, 1 -> row r+8
                int lr = wm * 32 + i * 16 + hi * 8 + gid;
                int grow = rowBase + lr;
                float thv = th[i * 2 + hi];
                #pragma unroll
                for (int j = 0; j < 4; j++) {
                    float2 vv = __half22float2(*(__half2*)&c[i][j][hi]);
                    #pragma unroll
                    for (int e = 0; e < 2; e++) {
                        int gc = colBase + wn * 32 + j * 8 + 2 * tig + e;
                        float v = (e == 0) ? vv.x : vv.y;
                        if (gc < colEnd && gc != grow && v > thv) {
                            int slot = atomicAdd(&cnt[lr], 1);
                            if (slot < CAP) { bufv[lr * CAP + slot] = v; bufi[lr * CAP + slot] = gc; }
                        }
                    }
                }
            }
        }
        __syncthreads();
        // ---- compaction: one thread per row ----
        if (tid < BM) {
            int cc = cnt[tid];
            if (cc > 0) {
                if (cc > CAP) cc = CAP;
                int nf = nfill[tid];
                float* tv = topv + tid * TKP;
                int*   ti = topi + tid * TKP;
                for (int s = 0; s < cc; s++) {
                    float v = bufv[tid * CAP + s];
                    int gi = bufi[tid * CAP + s];
                    if (nf == TKP && !precede(v, gi, tv[TKP - 1], ti[TKP - 1])) continue;
                    int p = (nf < TKP) ? nf : TKP - 1;
                    while (p > 0 && precede(v, gi, tv[p - 1], ti[p - 1])) {
                        tv[p] = tv[p - 1]; ti[p] = ti[p - 1]; p--;
                    }
                    tv[p] = v; ti[p] = gi;
                    if (nf < TKP) nf++;
                }
                nfill[tid] = nf;
                cnt[tid] = 0;
                if (nf == TKP) thresh[tid] = tv[TKP - 1];
            }
        }
        __syncthreads();
    }
    if (tid < BM) {
        int row = rowBase + tid;
        int nf = nfill[tid];
        for (int k2 = 0; k2 < TKP; k2++) {
            g_pv[(row * NSPLIT + split) * TKP + k2] = (k2 < nf) ? topv[tid * TKP + k2] : -CUDART_INF_F;
            g_pi[(row * NSPLIT + split) * TKP + k2] = (k2 < nf) ? topi[tid * TKP + k2] : 0x7fffffff;
        }
    }
}

// ---------------------------------------------------------------------------
// fp16 MMA centers GEMM + fused min-2 of (c2 - 2*dot) per split
// grid (NA/BM, NSPLIT_C), 256 threads, static smem
// ---------------------------------------------------------------------------
__global__ __launch_bounds__(256)
void k_centers(void) {
    __shared__ __align__(16) uint16_t As[2 * 64 * SAPAD];
    __shared__ __align__(16) uint16_t Bs[2 * 128 * SBPAD];
    __shared__ float redv[BM * 32];
    __shared__ int   redi[BM * 32];

    int tid = threadIdx.x;
    int lane = tid & 31, wid = tid >> 5;
    int gid = lane >> 2, tig = lane & 3;
    int wm = wid & 1, wn = wid >> 1;
    int ar = tid >> 2, aq = tid & 3;

    int aRow0 = (lane & 7) + ((lane >> 3) & 1) * 8;
    int aKsel = (lane >> 4) * 8;
    int bRow0 = (lane & 7) + ((lane >> 3) >> 1) * 8;
    int bKsel = ((lane >> 3) & 1) * 8;

    int rowBase = blockIdx.x * BM;
    int split = blockIdx.y;
    int colStart = split * CHUNK_C;
    int colEnd = colStart + CHUNK_C;

    uint32_t sA = (uint32_t)__cvta_generic_to_shared(As);
    uint32_t sB = (uint32_t)__cvta_generic_to_shared(Bs);

    float bv0[4], bv1[4]; int bi0[4], bi1[4];
    #pragma unroll
    for (int i = 0; i < 4; i++) {
        bv0[i] = bv1[i] = CUDART_INF_F;
        bi0[i] = bi1[i] = 0x7fffffff;
    }

    int nT = (CHUNK_C + BN - 1) / BN;
    for (int t = 0; t < nT; t++) {
        int colBase = colStart + t * BN;
        uint32_t c[2][4][2];
        #pragma unroll
        for (int i = 0; i < 2; i++)
            #pragma unroll
            for (int j = 0; j < 4; j++) { c[i][j][0] = 0u; c[i][j][1] = 0u; }

        auto issueAB = [&](int st, int kt) {
            uint32_t dstA = sA + (uint32_t)(st * 64 * SAPAD + ar * SAPAD + aq * 8) * 2;
            const uint16_t* srcA = g_Ah + (size_t)(rowBase + ar) * D + kt + aq * 8;
            cp16(dstA, srcA, 16);
            #pragma unroll
            for (int h = 0; h < 2; h++) {
                int r = ar + h * 64;
                int gc = colBase + r;
                bool ok = gc < colEnd;
                uint32_t dstB = sB + (uint32_t)(st * 128 * SBPAD + r * SBPAD + aq * 8) * 2;
                const uint16_t* srcB = g_Cenh + (size_t)(ok ? gc : 0) * D + kt + aq * 8;
                cp16(dstB, srcB, ok ? 16 : 0);
            }
            cp_commit();
        };

        issueAB(0, 0);
        for (int kk = 0; kk < NKC; kk++) {
            int cur = kk & 1;
            if (kk + 1 < NKC) {
                issueAB((kk + 1) & 1, (kk + 1) * BK);
                asm volatile("cp.async.wait_group 1;" ::: "memory");
            } else {
                asm volatile("cp.async.wait_group 0;" ::: "memory");
            }
            __syncthreads();
            uint32_t sAc = sA + (uint32_t)(cur * 64 * SAPAD) * 2;
            uint32_t sBc = sB + (uint32_t)(cur * 128 * SBPAD) * 2;
            #pragma unroll
            for (int ks = 0; ks < 2; ks++) {
                int k0 = ks * 16;
                uint32_t af[2][4], fb[4][2];
                #pragma unroll
                for (int i = 0; i < 2; i++)
                    ldsm_x4(af[i], sAc + (uint32_t)((wm * 32 + i * 16 + aRow0) * SAPAD
                                                    + k0 + aKsel) * 2);
                #pragma unroll
                for (int jp = 0; jp < 2; jp++) {
                    uint32_t tmp[4];
                    ldsm_x4(tmp, sBc + (uint32_t)((wn * 32 + jp * 16 + bRow0) * SBPAD
                                                  + k0 + bKsel) * 2);
                    fb[2 * jp][0] = tmp[0]; fb[2 * jp][1] = tmp[1];
                    fb[2 * jp + 1][0] = tmp[2]; fb[2 * jp + 1][1] = tmp[3];
                }
                #pragma unroll
                for (int i = 0; i < 2; i++)
                    #pragma unroll
                    for (int j = 0; j < 4; j++)
                        mma16816h(c[i][j], af[i], fb[j]);
            }
            __syncthreads();
        }

        // min-2 update (unpack f16 accums)
        #pragma unroll
        for (int i = 0; i < 2; i++)
            #pragma unroll
            for (int hi = 0; hi < 2; hi++) {
                int ri = i * 2 + hi;
                #pragma unroll
                for (int j = 0; j < 4; j++) {
                    float2 vv = __half22float2(*(__half2*)&c[i][j][hi]);
                    #pragma unroll
                    for (int e = 0; e < 2; e++) {
                        int gc = colBase + wn * 32 + j * 8 + 2 * tig + e;
                        if (gc < colEnd) {
                            float dotv = (e == 0) ? vv.x : vv.y;
                            float v = g_c2[gc] - 2.0f * dotv;
                            if (v < bv0[ri] || (v == bv0[ri] && gc < bi0[ri])) {
                                bv1[ri] = bv0[ri]; bi1[ri] = bi0[ri];
                                bv0[ri] = v; bi0[ri] = gc;
                            } else if (v < bv1[ri] || (v == bv1[ri] && gc < bi1[ri])) {
                                bv1[ri] = v; bi1[ri] = gc;
                            }
                        }
                    }
                }
            }
    }

    // reduction across the 16 thread-columns holding each row
    int sid = wn * 4 + tig;   // 0..15
    #pragma unroll
    for (int i = 0; i < 2; i++)
        #pragma unroll
        for (int hi = 0; hi < 2; hi++) {
            int ri = i * 2 + hi;
            int lr = wm * 32 + i * 16 + hi * 8 + gid;
            redv[lr * 32 + sid * 2 + 0] = bv0[ri];
            redi[lr * 32 + sid * 2 + 0] = bi0[ri];
            redv[lr * 32 + sid * 2 + 1] = bv1[ri];
            redi[lr * 32 + sid * 2 + 1] = bi1[ri];
        }
    __syncthreads();
    if (tid < BM) {
        float b0 = CUDART_INF_F, b1 = CUDART_INF_F;
        int i0 = 0x7fffffff, i1 = 0x7fffffff;
        for (int x = 0; x < 32; x++) {
            float v = redv[tid * 32 + x]; int ii = redi[tid * 32 + x];
            if (v < b0 || (v == b0 && ii < i0)) { b1 = b0; i1 = i0; b0 = v; i0 = ii; }
            else if (v < b1 || (v == b1 && ii < i1)) { b1 = v; i1 = ii; }
        }
        int row = rowBase + tid;
        g_cmv[(row * NSPLIT_C + split) * 2 + 0] = b0;
        g_cmi[(row * NSPLIT_C + split) * 2 + 0] = i0;
        g_cmv[(row * NSPLIT_C + split) * 2 + 1] = b1;
        g_cmi[(row * NSPLIT_C + split) * 2 + 1] = i1;
    }
}

// ---------------------------------------------------------------------------
// Merge topk partials: bitonic sort of 256 pairs/row, keep top-32
// ---------------------------------------------------------------------------
__global__ void k_mtopk() {
    __shared__ float sv[256];
    __shared__ int   si[256];
    int row = blockIdx.x;
    int tid = threadIdx.x;
    sv[tid] = g_pv[row * 256 + tid];
    si[tid] = g_pi[row * 256 + tid];
    __syncthreads();
    for (int k = 2; k <= 256; k <<= 1) {
        for (int j = k >> 1; j > 0; j >>= 1) {
            int ixj = tid ^ j;
            if (ixj > tid) {
                float v1 = sv[tid], v2 = sv[ixj];
                int i1 = si[tid], i2 = si[ixj];
                bool desc = ((tid & k) == 0);
                bool sw = desc ? precede(v2, i2, v1, i1) : precede(v1, i1, v2, i2);
                if (sw) { sv[tid] = v2; si[tid] = i2; sv[ixj] = v1; si[ixj] = i1; }
            }
            __syncthreads();
        }
    }
    if (tid < TKP) g_ridx[row * TKP + tid] = si[tid];
}

// ---------------------------------------------------------------------------
// compensated-fp32 dot / dist2 (TwoProd via FMA + Neumaier; exact-class rank)
// ---------------------------------------------------------------------------
__device__ __forceinline__ double comp_dot(const float* __restrict__ a,
                                           const float* __restrict__ b, int lane) {
    float s = 0.f, comp = 0.f;
    for (int k = lane; k < D; k += 32) {
        float x = a[k], y = b[k];
        float p = x * y;
        float e = fmaf(x, y, -p);
        float t = s + p;
        comp += (fabsf(s) >= fabsf(p)) ? ((s - t) + p) : ((p - t) + s);
        s = t;
        comp += e;
    }
    return (double)s + (double)comp;
}

__device__ __forceinline__ double comp_dist2(const float* __restrict__ a,
                                             const float* __restrict__ b, int lane) {
    float s = 0.f, comp = 0.f;
    for (int k = lane; k < D; k += 32) {
        float d = a[k] - b[k];
        float p = d * d;
        float e = fmaf(d, d, -p);
        float t = s + p;
        comp += (fabsf(s) >= fabsf(p)) ? ((s - t) + p) : ((p - t) + s);
        s = t;
        comp += e;
    }
    return (double)s + (double)comp;
}

// ---------------------------------------------------------------------------
// refine top-32 sims -> exact top-16 (one block per anchor row)
// ---------------------------------------------------------------------------
__global__ __launch_bounds__(256)
void k_refine(const float* __restrict__ A, const float* __restrict__ Cand) {
    __shared__ double dv[TKP];
    __shared__ int    di[TKP];
    int row = blockIdx.x;
    int tid = threadIdx.x;
    int wid = tid >> 5, lane = tid & 31;
    const float* ar = A + (size_t)row * D;
    for (int c = wid; c < TKP; c += 8) {
        int idx = g_ridx[row * TKP + c];
        double s;
        if (idx >= 0 && idx < NC) {
            s = comp_dot(ar, Cand + (size_t)idx * D, lane);
        } else {
            s = (lane == 0) ? -CUDART_INF : 0.0;
        }
        #pragma unroll
        for (int o = 16; o; o >>= 1) s += __shfl_down_sync(0xffffffffu, s, o);
        if (lane == 0) { dv[c] = s; di[c] = idx; }
    }
    __syncthreads();
    if (tid == 0) {
        double tvv[TK]; int tii[TK]; int nf = 0;
        for (int s = 0; s < TKP; s++) {
            double v = dv[s]; int gi = di[s];
            if (nf == TK && !preceded(v, gi, tvv[TK - 1], tii[TK - 1])) continue;
            int p = (nf < TK) ? nf : TK - 1;
            while (p > 0 && preceded(v, gi, tvv[p - 1], tii[p - 1])) {
                tvv[p] = tvv[p - 1]; tii[p] = tii[p - 1]; p--;
            }
            tvv[p] = v; tii[p] = gi;
            if (nf < TK) nf++;
        }
        for (int k2 = 0; k2 < TK; k2++) g_fidx[row * TK + k2] = tii[k2];
    }
}

// ---------------------------------------------------------------------------
// refine 16 center candidates -> exact argmin + min_dist
// ---------------------------------------------------------------------------
__global__ __launch_bounds__(256)
void k_cenref(const float* __restrict__ A, const float* __restrict__ Cen,
              float* __restrict__ out) {
    __shared__ double dv[NSPLIT_C * 2];
    __shared__ int    di[NSPLIT_C * 2];
    int row = blockIdx.x;
    int tid = threadIdx.x;
    int wid = tid >> 5, lane = tid & 31;
    const float* ar = A + (size_t)row * D;
    for (int c = wid; c < NSPLIT_C * 2; c += 8) {
        int idx = g_cmi[row * NSPLIT_C * 2 + c];
        double s;
        if (idx >= 0 && idx < NCEN) {
            s = comp_dist2(ar, Cen + (size_t)idx * D, lane);
        } else {
            s = (lane == 0) ? CUDART_INF : 0.0;
        }
        #pragma unroll
        for (int o = 16; o; o >>= 1) s += __shfl_down_sync(0xffffffffu, s, o);
        if (lane == 0) { dv[c] = s; di[c] = idx; }
    }
    __syncthreads();
    if (tid == 0) {
        double best = CUDART_INF; int besti = 0x7fffffff;
        for (int s = 0; s < NSPLIT_C * 2; s++) {
            double v = dv[s]; int ii = di[s];
            if (v < best || (v == best && ii < besti)) { best = v; besti = ii; }
        }
        if (best < 0.0) best = 0.0;
        out[(size_t)NA * TK * D + row] = (float)besti;
        out[(size_t)NA * TK * D + NA + row] = (float)sqrt(best);
    }
}

// ---------------------------------------------------------------------------
// Gather: out[row][k][:] = candidates[idx][:]
// ---------------------------------------------------------------------------
__global__ void k_gather(const float* __restrict__ Cand, float* __restrict__ out) {
    int b = blockIdx.x;
    int t = threadIdx.x;
    int idx = g_fidx[b];
    const float4* c4 = (const float4*)(Cand + (size_t)idx * D);
    float4* o4 = (float4*)(out + (size_t)b * D);
    o4[t] = c4[t];
}

// ---------------------------------------------------------------------------
extern "C" void kernel_launch(void* const* d_in, const int* in_sizes, int n_in,
                              void* d_out, int out_size) {
    const float* A    = (const float*)d_in[0];   // anchors    [4096, 768]
    const float* Cand = (const float*)d_in[1];   // candidates [50000, 768]
    const float* Cen  = (const float*)d_in[2];   // centers    [10000, 768]
    float* out = (float*)d_out;

    // dynamic smem for k_topk
    int smem_topk = (2 * 64 * SAPAD + 2 * 128 * SBPAD) * 2          // fp16 tiles
                  + (2 * BM * TKP + 2 * BM * CAP + 3 * BM) * 4;     // topk state
    cudaFuncSetAttribute(k_topk, cudaFuncAttributeMaxDynamicSharedMemorySize, smem_topk);

    uint16_t *pAh, *pCandh, *pCenh;
    cudaGetSymbolAddress((void**)&pAh, g_Ah);
    cudaGetSymbolAddress((void**)&pCandh, g_Candh);
    cudaGetSymbolAddress((void**)&pCenh, g_Cenh);

    // launches 1-3: conversions to fp16
    k_cvt<<<(NA * D / 4 + 255) / 256, 256>>>((const float4*)A, (uint2*)pAh, NA * D / 4);
    k_cvt<<<(NC * D / 4 + 255) / 256, 256>>>((const float4*)Cand, (uint2*)pCandh, NC * D / 4);
    k_cvt<<<(NCEN * D / 4 + 255) / 256, 256>>>((const float4*)Cen, (uint2*)pCenh, NCEN * D / 4);
    // launch 4 (ncu capture slot): candidates GEMM + top-32 pruning
    k_topk<<<dim3(NA / BM, NSPLIT), 256, smem_topk>>>();
    // ||center||^2, then centers GEMM + min-2 pruning
    k_c2<<<(NCEN * 32 + 255) / 256, 256>>>(Cen);
    k_centers<<<dim3(NA / BM, NSPLIT_C), 256>>>();
    // merge partials -> refine list
    k_mtopk<<<NA, 256>>>();
    // exact top-16 (compensated fp32)
    k_refine<<<NA, 256>>>(A, Cand);
    // exact argmin + min_dist
    k_cenref<<<NA, 256>>>(A, Cen, out);
    // gather hard negatives
    k_gather<<<NA * TK, 192>>>(Cand, out);
}